// round 10
// baseline (speedup 1.0000x reference)
#include <cuda_runtime.h>
#include <cstdint>

#define SEQ  4096
#define DIM  1024
#define NH   16
#define HD   64

// Scratch (allocation-free rule: __device__ globals)
__device__ float g_q[(size_t)NH * SEQ * HD];   // [H][SEQ][HD] tf32, pre-scaled 0.125
__device__ float g_k[(size_t)NH * SEQ * HD];   // [H][SEQ][HD] tf32
__device__ float g_v[(size_t)NH * HD * SEQ];   // [H][HD][SEQ] tf32 (d-major!)
__device__ float g_att[(size_t)SEQ * DIM];     // tf32 (attn epilogue)
__device__ float g_x [(size_t)SEQ * DIM];
__device__ float g_wq[(size_t)DIM * 3 * DIM];
__device__ float g_wp[(size_t)DIM * DIM];

// ---------------------------------------------------------------------------
__device__ __forceinline__ uint32_t smem_u32(const void* p) {
    uint32_t a;
    asm("{ .reg .u64 t; cvta.to.shared.u64 t, %1; cvt.u32.u64 %0, t; }" : "=r"(a) : "l"(p));
    return a;
}
__device__ __forceinline__ float ex2f(float x) {
    float r; asm("ex2.approx.ftz.f32 %0, %1;" : "=f"(r) : "f"(x)); return r;
}
__device__ __forceinline__ float tf32_rna(float x) {
    uint32_t u; asm("cvt.rna.tf32.f32 %0, %1;" : "=r"(u) : "f"(x)); return __uint_as_float(u);
}
__device__ __forceinline__ void cp16(uint32_t dst, const void* src) {
    asm volatile("cp.async.cg.shared.global [%0], [%1], 16;" :: "r"(dst), "l"(src));
}
#define CP_COMMIT() asm volatile("cp.async.commit_group;" ::: "memory")
#define CP_WAITG1() asm volatile("cp.async.wait_group 1;" ::: "memory")

__device__ __forceinline__ void mma_tf32(float* d, const float* a, float b0, float b1) {
    asm volatile(
        "mma.sync.aligned.m16n8k8.row.col.f32.tf32.tf32.f32 "
        "{%0,%1,%2,%3}, {%4,%5,%6,%7}, {%8,%9}, {%0,%1,%2,%3};"
        : "+f"(d[0]), "+f"(d[1]), "+f"(d[2]), "+f"(d[3])
        : "r"(__float_as_uint(a[0])), "r"(__float_as_uint(a[1])),
          "r"(__float_as_uint(a[2])), "r"(__float_as_uint(a[3])),
          "r"(__float_as_uint(b0)), "r"(__float_as_uint(b1)));
}

#define LOG2E 1.44269504f

// ---------------------------------------------------------------------------
// Pre-round x / W_qkv / W_proj to tf32 (RNA) once per launch.
// ---------------------------------------------------------------------------
#define XN   ((size_t)SEQ * DIM)
#define WQN  ((size_t)DIM * 3 * DIM)
#define WPN  ((size_t)DIM * DIM)
#define TOT4 ((XN + WQN + WPN) / 4)

__global__ __launch_bounds__(256) void pre_round(const float* __restrict__ x,
                                                 const float* __restrict__ wq,
                                                 const float* __restrict__ wp) {
    size_t i = (size_t)blockIdx.x * blockDim.x + threadIdx.x;
    if (i >= TOT4) return;
    const float* src;
    float* dst;
    size_t off;
    if (i < XN / 4)                { src = x;  dst = g_x;  off = i; }
    else if (i < (XN + WQN) / 4)   { src = wq; dst = g_wq; off = i - XN / 4; }
    else                           { src = wp; dst = g_wp; off = i - (XN + WQN) / 4; }
    float4 v = ((const float4*)src)[off];
    v.x = tf32_rna(v.x); v.y = tf32_rna(v.y);
    v.z = tf32_rna(v.z); v.w = tf32_rna(v.w);
    ((float4*)dst)[off] = v;
}

// ---------------------------------------------------------------------------
// tf32 warp-MMA GEMM, 3-stage / single-barrier-per-chunk pipeline (round 9).
// ---------------------------------------------------------------------------
#define ASTR 24
#define BSTR 136
#define A_ST_F (128 * ASTR)
#define B_ST_F (16 * BSTR)
#define STG_F  (A_ST_F + B_ST_F)       // 5248 floats / stage
#define NCHUNK (DIM / 16)              // 64

template <int N_, int MODE>
__global__ __launch_bounds__(256) void gemm_tc(const float* __restrict__ bias,
                                               float* __restrict__ C) {
    extern __shared__ float sm[];
    const uint32_t sb = smem_u32(sm);
    const int K = DIM;
    const float* A = (MODE == 1) ? g_att : g_x;
    const float* B = (MODE == 1) ? g_wp : g_wq;

    const int t    = threadIdx.x;
    const int w    = t >> 5;
    const int lane = t & 31;
    const int lr   = lane >> 2;
    const int lc   = lane & 3;
    const int wm   = (w >> 2) * 64;
    const int wn   = (w & 3) * 32;
    const int rowBase = blockIdx.y * 128;
    const int colBase = blockIdx.x * 128;

    auto load_chunk = [&](int k0, int s) {
        uint32_t base = sb + (uint32_t)s * (STG_F * 4);
#pragma unroll
        for (int i = 0; i < 2; i++) {
            int id = t + i * 256;
            int r  = id >> 2;
            int c4 = id & 3;
            cp16(base + (uint32_t)r * (ASTR * 4) + (uint32_t)c4 * 16,
                 A + (size_t)(rowBase + r) * K + k0 + c4 * 4);
        }
#pragma unroll
        for (int i = 0; i < 2; i++) {
            int id = t + i * 256;
            int r  = id >> 5;
            int c4 = id & 31;
            int j  = r & 7;
            int rs = (r & 8) + ((j & 1) ? (j >> 1) + 4 : (j >> 1));
            cp16(base + (uint32_t)(A_ST_F * 4) + (uint32_t)rs * (BSTR * 4) + (uint32_t)c4 * 16,
                 B + (size_t)(k0 + r) * N_ + colBase + c4 * 4);
        }
        CP_COMMIT();
    };

    load_chunk(0, 0);
    load_chunk(16, 1);

    float acc[4][4][4];
#pragma unroll
    for (int mt = 0; mt < 4; mt++)
#pragma unroll
        for (int nt = 0; nt < 4; nt++)
#pragma unroll
            for (int i = 0; i < 4; i++) acc[mt][nt][i] = 0.f;

    for (int kc = 0; kc < NCHUNK; kc++) {
        const int s = kc % 3;
        const float* As = sm + s * STG_F;
        const float* Bs = As + A_ST_F;

        CP_WAITG1();
        __syncthreads();

        if (kc + 2 < NCHUNK) load_chunk((kc + 2) * 16, (kc + 2) % 3);
        else CP_COMMIT();

#pragma unroll
        for (int kk = 0; kk < 2; kk++) {
            const int k = kk * 8;
            float af[4][4];
#pragma unroll
            for (int mt = 0; mt < 4; mt++) {
                int mb = wm + mt * 16;
                float2 a0 = *(const float2*)&As[(mb + lr) * ASTR + k + 2 * lc];
                float2 a1 = *(const float2*)&As[(mb + lr + 8) * ASTR + k + 2 * lc];
                af[mt][0] = a0.x; af[mt][2] = a0.y;
                af[mt][1] = a1.x; af[mt][3] = a1.y;
            }
            float bf[4][2];
#pragma unroll
            for (int nt = 0; nt < 4; nt++) {
                int n = wn + nt * 8 + lr;
                bf[nt][0] = Bs[(k + lc) * BSTR + n];
                bf[nt][1] = Bs[(k + lc + 4) * BSTR + n];
            }
#pragma unroll
            for (int mt = 0; mt < 4; mt++)
#pragma unroll
                for (int nt = 0; nt < 4; nt++)
                    mma_tf32(acc[mt][nt], af[mt], bf[nt][0], bf[nt][1]);
        }
    }

    // Epilogue
#pragma unroll
    for (int nt = 0; nt < 4; nt++) {
        int c = colBase + wn + nt * 8 + 2 * lc;
        float2 bv = *(const float2*)&bias[c];
#pragma unroll
        for (int mt = 0; mt < 4; mt++) {
            int r0 = rowBase + wm + mt * 16 + lr;
            int r1 = r0 + 8;
            float v00 = acc[mt][nt][0] + bv.x, v01 = acc[mt][nt][1] + bv.y;
            float v10 = acc[mt][nt][2] + bv.x, v11 = acc[mt][nt][3] + bv.y;
            if (MODE == 0) {
                int which = c >> 10;
                int c2    = c & 1023;
                int head  = c2 >> 6;
                int d     = c2 & 63;
                if (which == 0) {
                    float* dq = g_q + ((size_t)head * SEQ) * HD + d;
                    *(float2*)&dq[(size_t)r0 * HD] =
                        make_float2(tf32_rna(v00 * 0.125f), tf32_rna(v01 * 0.125f));
                    *(float2*)&dq[(size_t)r1 * HD] =
                        make_float2(tf32_rna(v10 * 0.125f), tf32_rna(v11 * 0.125f));
                } else if (which == 1) {
                    float* dk = g_k + ((size_t)head * SEQ) * HD + d;
                    *(float2*)&dk[(size_t)r0 * HD] = make_float2(tf32_rna(v00), tf32_rna(v01));
                    *(float2*)&dk[(size_t)r1 * HD] = make_float2(tf32_rna(v10), tf32_rna(v11));
                } else {
                    float* dv = g_v + (size_t)head * HD * SEQ;
                    dv[(size_t)(d)     * SEQ + r0] = tf32_rna(v00);
                    dv[(size_t)(d + 1) * SEQ + r0] = tf32_rna(v01);
                    dv[(size_t)(d)     * SEQ + r1] = tf32_rna(v10);
                    dv[(size_t)(d + 1) * SEQ + r1] = tf32_rna(v11);
                }
            } else {
                *(float2*)&C[(size_t)r0 * N_ + c] = make_float2(v00, v01);
                *(float2*)&C[(size_t)r1 * N_ + c] = make_float2(v10, v11);
            }
        }
    }
}

// ---------------------------------------------------------------------------
// Warp-MMA tf32 flash attention: 32 q-rows per warp (2 m-tiles) so every
// K/V B-fragment LDS.64 feeds TWO MMAs. Register-resident P, 3-stage KV
// pipeline, one barrier/iter. Block = 128 q-rows x head, 4 warps.
// ---------------------------------------------------------------------------
#define PSTR 72
#define STAGE_F (2 * 64 * PSTR)        // 9216 floats (K + V)
#define ATTN_SM_F (3 * STAGE_F)        // 27648 floats = 110592 B

__global__ __launch_bounds__(128, 2) void attn_mma() {
    extern __shared__ float sm[];
    const uint32_t sb = smem_u32(sm);

    const int t    = threadIdx.x;
    const int lane = t & 31;
    const int lr   = lane >> 2;
    const int lc   = lane & 3;
    const int rb   = (t >> 5) * 32;    // warp's 32-row base
    const int h  = blockIdx.y;
    const int qt = blockIdx.x;

    const float* Kh = g_k + (size_t)h * SEQ * HD;   // [key][d]
    const float* Vh = g_v + (size_t)h * HD * SEQ;   // [d][key]

    auto load_stage = [&](int kt2, int s) {
#pragma unroll
        for (int i = 0; i < 16; i++) {
            int id   = t + i * 128;            // 0..2047
            int tile = id >> 10;               // 0=K 1=V
            int r    = (id >> 4) & 63;
            int c4   = id & 15;
            uint32_t dst = sb + (uint32_t)s * (STAGE_F * 4)
                              + (uint32_t)tile * (64 * PSTR * 4)
                              + (uint32_t)r * (PSTR * 4) + (uint32_t)c4 * 16;
            const float* src = tile
                ? Vh + (size_t)r * SEQ + (size_t)kt2 * 64 + c4 * 4     // r = d
                : Kh + ((size_t)kt2 * 64 + r) * HD + c4 * 4;           // r = key
            cp16(dst, src);
        }
        CP_COMMIT();
    };

    load_stage(0, 0);
    load_stage(1, 1);

    // Stage 128 Q rows through the (not yet filled) stage-2 buffer (fits exactly)
    float* Qs = sm + 2 * STAGE_F;
    {
        const float* Qg = g_q + ((size_t)h * SEQ + (size_t)qt * 128) * HD;
#pragma unroll
        for (int i = 0; i < 16; i++) {
            int id = t + i * 128;              // float4 units, 0..2047
            int r  = id >> 4;                  // 0..127
            int c  = (id & 15) * 4;
            *(float4*)&Qs[r * PSTR + c] = *(const float4*)&Qg[(size_t)r * HD + c];
        }
    }
    __syncthreads();
    float qf[2][8][4];
#pragma unroll
    for (int mt = 0; mt < 2; mt++)
#pragma unroll
        for (int k = 0; k < 8; k++) {
            float2 a0 = *(const float2*)&Qs[(rb + mt * 16 + lr) * PSTR + k * 8 + 2 * lc];
            float2 a1 = *(const float2*)&Qs[(rb + mt * 16 + lr + 8) * PSTR + k * 8 + 2 * lc];
            qf[mt][k][0] = a0.x; qf[mt][k][2] = a0.y;
            qf[mt][k][1] = a1.x; qf[mt][k][3] = a1.y;
        }
    // iter-0's loop-top barrier orders these reads before stage-2's first fill

    float ob[2][8][4];
#pragma unroll
    for (int mt = 0; mt < 2; mt++)
#pragma unroll
        for (int j = 0; j < 8; j++)
#pragma unroll
            for (int i = 0; i < 4; i++) ob[mt][j][i] = 0.f;
    float accl[2][4] = {{0.f, 0.f, 0.f, 0.f}, {0.f, 0.f, 0.f, 0.f}};
    const float bl = (lr == 0) ? 1.f : 0.f;
    float m0[2] = {-1e30f, -1e30f}, m1[2] = {-1e30f, -1e30f};

    for (int kt = 0; kt < SEQ / 64; kt++) {
        const int s = kt % 3;
        const float* Ks = sm + s * STAGE_F;
        const float* Vs = Ks + 64 * PSTR;

        CP_WAITG1();          // tile kt resident
        __syncthreads();      // all warps past iter kt-1

        if (kt + 2 < SEQ / 64) load_stage(kt + 2, (kt + 2) % 3);
        else CP_COMMIT();

        // ---- S = Q * K^T : each K fragment feeds both m-tiles ----
        float sc[2][8][4];
#pragma unroll
        for (int mt = 0; mt < 2; mt++)
#pragma unroll
            for (int j = 0; j < 8; j++)
#pragma unroll
                for (int i = 0; i < 4; i++) sc[mt][j][i] = 0.f;
#pragma unroll
        for (int k = 0; k < 8; k++) {
#pragma unroll
            for (int j = 0; j < 8; j++) {
                float2 b = *(const float2*)&Ks[(j * 8 + lr) * PSTR + k * 8 + 2 * lc];
                mma_tf32(sc[0][j], qf[0][k], b.x, b.y);
                mma_tf32(sc[1][j], qf[1][k], b.x, b.y);
            }
        }

        // ---- online softmax per m-tile, P stays in registers ----
        float corr0[2], corr1[2];
#pragma unroll
        for (int mt = 0; mt < 2; mt++) {
            float mx0 = sc[mt][0][0], mx1 = sc[mt][0][2];
#pragma unroll
            for (int j = 0; j < 8; j++) {
                mx0 = fmaxf(mx0, fmaxf(sc[mt][j][0], sc[mt][j][1]));
                mx1 = fmaxf(mx1, fmaxf(sc[mt][j][2], sc[mt][j][3]));
            }
            mx0 = fmaxf(mx0, __shfl_xor_sync(0xffffffffu, mx0, 1));
            mx0 = fmaxf(mx0, __shfl_xor_sync(0xffffffffu, mx0, 2));
            mx1 = fmaxf(mx1, __shfl_xor_sync(0xffffffffu, mx1, 1));
            mx1 = fmaxf(mx1, __shfl_xor_sync(0xffffffffu, mx1, 2));
            float nm0 = fmaxf(m0[mt], mx0), nm1 = fmaxf(m1[mt], mx1);
            corr0[mt] = ex2f((m0[mt] - nm0) * LOG2E);
            corr1[mt] = ex2f((m1[mt] - nm1) * LOG2E);
#pragma unroll
            for (int j = 0; j < 8; j++) {
                sc[mt][j][0] = ex2f((sc[mt][j][0] - nm0) * LOG2E);
                sc[mt][j][1] = ex2f((sc[mt][j][1] - nm0) * LOG2E);
                sc[mt][j][2] = ex2f((sc[mt][j][2] - nm1) * LOG2E);
                sc[mt][j][3] = ex2f((sc[mt][j][3] - nm1) * LOG2E);
            }
            m0[mt] = nm0; m1[mt] = nm1;
#pragma unroll
            for (int j = 0; j < 8; j++) {
                ob[mt][j][0] *= corr0[mt]; ob[mt][j][1] *= corr0[mt];
                ob[mt][j][2] *= corr1[mt]; ob[mt][j][3] *= corr1[mt];
            }
            accl[mt][0] *= corr0[mt]; accl[mt][2] *= corr1[mt];
        }

        // ---- O += P*V ; l += P*1 : each V fragment feeds both m-tiles ----
#pragma unroll
        for (int k = 0; k < 8; k++) {
            float pf0[4], pf1[4];
            pf0[0] = sc[0][k][0]; pf0[1] = sc[0][k][2];
            pf0[2] = sc[0][k][1]; pf0[3] = sc[0][k][3];
            pf1[0] = sc[1][k][0]; pf1[1] = sc[1][k][2];
            pf1[2] = sc[1][k][1]; pf1[3] = sc[1][k][3];
#pragma unroll
            for (int j = 0; j < 8; j++) {
                float2 b = *(const float2*)&Vs[(j * 8 + lr) * PSTR + k * 8 + 2 * lc];
                mma_tf32(ob[0][j], pf0, b.x, b.y);
                mma_tf32(ob[1][j], pf1, b.x, b.y);
            }
            mma_tf32(accl[0], pf0, bl, bl);
            mma_tf32(accl[1], pf1, bl, bl);
        }
        // next iter's loop-top barrier covers stage reuse
    }

#pragma unroll
    for (int mt = 0; mt < 2; mt++) {
        float l0 = __shfl_sync(0xffffffffu, accl[mt][0], lane & 28);
        float l1 = __shfl_sync(0xffffffffu, accl[mt][2], lane & 28);
        float inv0 = 1.f / l0, inv1 = 1.f / l1;
        float* d0 = g_att + ((size_t)qt * 128 + rb + mt * 16 + lr) * DIM + h * HD;
        float* d1 = d0 + 8 * DIM;
#pragma unroll
        for (int j = 0; j < 8; j++) {
            *(float2*)&d0[j * 8 + lc * 2] =
                make_float2(tf32_rna(ob[mt][j][0] * inv0), tf32_rna(ob[mt][j][1] * inv0));
            *(float2*)&d1[j * 8 + lc * 2] =
                make_float2(tf32_rna(ob[mt][j][2] * inv1), tf32_rna(ob[mt][j][3] * inv1));
        }
    }
}

// ---------------------------------------------------------------------------
extern "C" void kernel_launch(void* const* d_in, const int* in_sizes, int n_in,
                              void* d_out, int out_size) {
    const float* x     = (const float*)d_in[0];
    const float* Wqkv  = (const float*)d_in[1];
    const float* bqkv  = (const float*)d_in[2];
    const float* Wproj = (const float*)d_in[3];
    const float* bproj = (const float*)d_in[4];
    float* out = (float*)d_out;

    const int gemm_shm = 3 * STG_F * (int)sizeof(float);        // 62976 B
    const int attn_shm = ATTN_SM_F * (int)sizeof(float);        // 110592 B

    // 0) pre-round x / W_qkv / W_proj to tf32
    pre_round<<<(int)((TOT4 + 255) / 256), 256>>>(x, Wqkv, Wproj);

    // 1) QKV projection (tf32 MMA, 3-stage pipeline)
    cudaFuncSetAttribute(gemm_tc<3 * DIM, 0>, cudaFuncAttributeMaxDynamicSharedMemorySize, gemm_shm);
    gemm_tc<3 * DIM, 0><<<dim3(24, 32), 256, gemm_shm>>>(bqkv, nullptr);

    // 2) warp-MMA tf32 flash attention (32 q-rows/warp)
    cudaFuncSetAttribute(attn_mma, cudaFuncAttributeMaxDynamicSharedMemorySize, attn_shm);
    attn_mma<<<dim3(SEQ / 128, NH), 128, attn_shm>>>();

    // 3) Output projection (tf32 MMA, 3-stage pipeline)
    cudaFuncSetAttribute(gemm_tc<DIM, 1>, cudaFuncAttributeMaxDynamicSharedMemorySize, gemm_shm);
    gemm_tc<DIM, 1><<<dim3(8, 32), 256, gemm_shm>>>(bproj, out);
}

// round 11
// speedup vs baseline: 1.0240x; 1.0240x over previous
#include <cuda_runtime.h>
#include <cstdint>

#define SEQ  4096
#define DIM  1024
#define NH   16
#define HD   64

// Scratch (allocation-free rule: __device__ globals)
__device__ float g_q[(size_t)NH * SEQ * HD];   // [H][SEQ][HD] tf32, pre-scaled 0.125
__device__ float g_k[(size_t)NH * SEQ * HD];   // [H][SEQ][HD] tf32
__device__ float g_v[(size_t)NH * HD * SEQ];   // [H][HD][SEQ] tf32 (d-major!)
__device__ float g_att[(size_t)SEQ * DIM];     // tf32 (attn epilogue)
__device__ float g_x [(size_t)SEQ * DIM];
__device__ float g_wq[(size_t)DIM * 3 * DIM];
__device__ float g_wp[(size_t)DIM * DIM];

// ---------------------------------------------------------------------------
__device__ __forceinline__ uint32_t smem_u32(const void* p) {
    uint32_t a;
    asm("{ .reg .u64 t; cvta.to.shared.u64 t, %1; cvt.u32.u64 %0, t; }" : "=r"(a) : "l"(p));
    return a;
}
__device__ __forceinline__ float ex2f(float x) {
    float r; asm("ex2.approx.ftz.f32 %0, %1;" : "=f"(r) : "f"(x)); return r;
}
__device__ __forceinline__ float tf32_rna(float x) {
    uint32_t u; asm("cvt.rna.tf32.f32 %0, %1;" : "=r"(u) : "f"(x)); return __uint_as_float(u);
}
__device__ __forceinline__ void cp16(uint32_t dst, const void* src) {
    asm volatile("cp.async.cg.shared.global [%0], [%1], 16;" :: "r"(dst), "l"(src));
}
#define CP_COMMIT() asm volatile("cp.async.commit_group;" ::: "memory")
#define CP_WAITG1() asm volatile("cp.async.wait_group 1;" ::: "memory")

__device__ __forceinline__ void mma_tf32(float* d, const float* a, float b0, float b1) {
    asm volatile(
        "mma.sync.aligned.m16n8k8.row.col.f32.tf32.tf32.f32 "
        "{%0,%1,%2,%3}, {%4,%5,%6,%7}, {%8,%9}, {%0,%1,%2,%3};"
        : "+f"(d[0]), "+f"(d[1]), "+f"(d[2]), "+f"(d[3])
        : "r"(__float_as_uint(a[0])), "r"(__float_as_uint(a[1])),
          "r"(__float_as_uint(a[2])), "r"(__float_as_uint(a[3])),
          "r"(__float_as_uint(b0)), "r"(__float_as_uint(b1)));
}

#define LOG2E 1.44269504f

// ---------------------------------------------------------------------------
// Pre-round x / W_qkv / W_proj to tf32 (RNA) once per launch.
// ---------------------------------------------------------------------------
#define XN   ((size_t)SEQ * DIM)
#define WQN  ((size_t)DIM * 3 * DIM)
#define WPN  ((size_t)DIM * DIM)
#define TOT4 ((XN + WQN + WPN) / 4)

__global__ __launch_bounds__(256) void pre_round(const float* __restrict__ x,
                                                 const float* __restrict__ wq,
                                                 const float* __restrict__ wp) {
    size_t i = (size_t)blockIdx.x * blockDim.x + threadIdx.x;
    if (i >= TOT4) return;
    const float* src;
    float* dst;
    size_t off;
    if (i < XN / 4)                { src = x;  dst = g_x;  off = i; }
    else if (i < (XN + WQN) / 4)   { src = wq; dst = g_wq; off = i - XN / 4; }
    else                           { src = wp; dst = g_wp; off = i - (XN + WQN) / 4; }
    float4 v = ((const float4*)src)[off];
    v.x = tf32_rna(v.x); v.y = tf32_rna(v.y);
    v.z = tf32_rna(v.z); v.w = tf32_rna(v.w);
    ((float4*)dst)[off] = v;
}

// ---------------------------------------------------------------------------
// tf32 warp-MMA GEMM, 3-stage / single-barrier-per-chunk pipeline (round 9).
// ---------------------------------------------------------------------------
#define ASTR 24
#define BSTR 136
#define A_ST_F (128 * ASTR)
#define B_ST_F (16 * BSTR)
#define STG_F  (A_ST_F + B_ST_F)       // 5248 floats / stage
#define NCHUNK (DIM / 16)              // 64

template <int N_, int MODE>
__global__ __launch_bounds__(256) void gemm_tc(const float* __restrict__ bias,
                                               float* __restrict__ C) {
    extern __shared__ float sm[];
    const uint32_t sb = smem_u32(sm);
    const int K = DIM;
    const float* A = (MODE == 1) ? g_att : g_x;
    const float* B = (MODE == 1) ? g_wp : g_wq;

    const int t    = threadIdx.x;
    const int w    = t >> 5;
    const int lane = t & 31;
    const int lr   = lane >> 2;
    const int lc   = lane & 3;
    const int wm   = (w >> 2) * 64;
    const int wn   = (w & 3) * 32;
    const int rowBase = blockIdx.y * 128;
    const int colBase = blockIdx.x * 128;

    auto load_chunk = [&](int k0, int s) {
        uint32_t base = sb + (uint32_t)s * (STG_F * 4);
#pragma unroll
        for (int i = 0; i < 2; i++) {
            int id = t + i * 256;
            int r  = id >> 2;
            int c4 = id & 3;
            cp16(base + (uint32_t)r * (ASTR * 4) + (uint32_t)c4 * 16,
                 A + (size_t)(rowBase + r) * K + k0 + c4 * 4);
        }
#pragma unroll
        for (int i = 0; i < 2; i++) {
            int id = t + i * 256;
            int r  = id >> 5;
            int c4 = id & 31;
            int j  = r & 7;
            int rs = (r & 8) + ((j & 1) ? (j >> 1) + 4 : (j >> 1));
            cp16(base + (uint32_t)(A_ST_F * 4) + (uint32_t)rs * (BSTR * 4) + (uint32_t)c4 * 16,
                 B + (size_t)(k0 + r) * N_ + colBase + c4 * 4);
        }
        CP_COMMIT();
    };

    load_chunk(0, 0);
    load_chunk(16, 1);

    float acc[4][4][4];
#pragma unroll
    for (int mt = 0; mt < 4; mt++)
#pragma unroll
        for (int nt = 0; nt < 4; nt++)
#pragma unroll
            for (int i = 0; i < 4; i++) acc[mt][nt][i] = 0.f;

    for (int kc = 0; kc < NCHUNK; kc++) {
        const int s = kc % 3;
        const float* As = sm + s * STG_F;
        const float* Bs = As + A_ST_F;

        CP_WAITG1();
        __syncthreads();

        if (kc + 2 < NCHUNK) load_chunk((kc + 2) * 16, (kc + 2) % 3);
        else CP_COMMIT();

#pragma unroll
        for (int kk = 0; kk < 2; kk++) {
            const int k = kk * 8;
            float af[4][4];
#pragma unroll
            for (int mt = 0; mt < 4; mt++) {
                int mb = wm + mt * 16;
                float2 a0 = *(const float2*)&As[(mb + lr) * ASTR + k + 2 * lc];
                float2 a1 = *(const float2*)&As[(mb + lr + 8) * ASTR + k + 2 * lc];
                af[mt][0] = a0.x; af[mt][2] = a0.y;
                af[mt][1] = a1.x; af[mt][3] = a1.y;
            }
            float bf[4][2];
#pragma unroll
            for (int nt = 0; nt < 4; nt++) {
                int n = wn + nt * 8 + lr;
                bf[nt][0] = Bs[(k + lc) * BSTR + n];
                bf[nt][1] = Bs[(k + lc + 4) * BSTR + n];
            }
#pragma unroll
            for (int mt = 0; mt < 4; mt++)
#pragma unroll
                for (int nt = 0; nt < 4; nt++)
                    mma_tf32(acc[mt][nt], af[mt], bf[nt][0], bf[nt][1]);
        }
    }

    // Epilogue
#pragma unroll
    for (int nt = 0; nt < 4; nt++) {
        int c = colBase + wn + nt * 8 + 2 * lc;
        float2 bv = *(const float2*)&bias[c];
#pragma unroll
        for (int mt = 0; mt < 4; mt++) {
            int r0 = rowBase + wm + mt * 16 + lr;
            int r1 = r0 + 8;
            float v00 = acc[mt][nt][0] + bv.x, v01 = acc[mt][nt][1] + bv.y;
            float v10 = acc[mt][nt][2] + bv.x, v11 = acc[mt][nt][3] + bv.y;
            if (MODE == 0) {
                int which = c >> 10;
                int c2    = c & 1023;
                int head  = c2 >> 6;
                int d     = c2 & 63;
                if (which == 0) {
                    float* dq = g_q + ((size_t)head * SEQ) * HD + d;
                    *(float2*)&dq[(size_t)r0 * HD] =
                        make_float2(tf32_rna(v00 * 0.125f), tf32_rna(v01 * 0.125f));
                    *(float2*)&dq[(size_t)r1 * HD] =
                        make_float2(tf32_rna(v10 * 0.125f), tf32_rna(v11 * 0.125f));
                } else if (which == 1) {
                    float* dk = g_k + ((size_t)head * SEQ) * HD + d;
                    *(float2*)&dk[(size_t)r0 * HD] = make_float2(tf32_rna(v00), tf32_rna(v01));
                    *(float2*)&dk[(size_t)r1 * HD] = make_float2(tf32_rna(v10), tf32_rna(v11));
                } else {
                    float* dv = g_v + (size_t)head * HD * SEQ;
                    dv[(size_t)(d)     * SEQ + r0] = tf32_rna(v00);
                    dv[(size_t)(d + 1) * SEQ + r0] = tf32_rna(v01);
                    dv[(size_t)(d)     * SEQ + r1] = tf32_rna(v10);
                    dv[(size_t)(d + 1) * SEQ + r1] = tf32_rna(v11);
                }
            } else {
                *(float2*)&C[(size_t)r0 * N_ + c] = make_float2(v00, v01);
                *(float2*)&C[(size_t)r1 * N_ + c] = make_float2(v10, v11);
            }
        }
    }
}

// ---------------------------------------------------------------------------
// Warp-MMA tf32 flash attention (round-9 per-warp code, 256-thread blocks):
// 8 warps x 16 q-rows = 128 q-rows/block. Register-resident P, 3-stage KV
// pipeline, one barrier/iter. 2 blocks/SM -> 16 warps/SM (4 per SMSP).
// K/V tile loads amortized over 2x the q-rows (global traffic halved).
// ---------------------------------------------------------------------------
#define PSTR 72
#define STAGE_F (2 * 64 * PSTR)        // 9216 floats (K + V)
#define ATTN_SM_F (3 * STAGE_F)        // 27648 floats = 110592 B

__global__ __launch_bounds__(256, 2) void attn_mma() {
    extern __shared__ float sm[];
    const uint32_t sb = smem_u32(sm);

    const int t    = threadIdx.x;
    const int lane = t & 31;
    const int lr   = lane >> 2;
    const int lc   = lane & 3;
    const int w16  = (t >> 5) * 16;    // warp row base, 0..112
    const int h  = blockIdx.y;
    const int qt = blockIdx.x;

    const float* Kh = g_k + (size_t)h * SEQ * HD;   // [key][d]
    const float* Vh = g_v + (size_t)h * HD * SEQ;   // [d][key]

    auto load_stage = [&](int kt2, int s) {
#pragma unroll
        for (int i = 0; i < 8; i++) {
            int id   = t + i * 256;            // 0..2047
            int tile = id >> 10;               // 0=K 1=V
            int r    = (id >> 4) & 63;
            int c4   = id & 15;
            uint32_t dst = sb + (uint32_t)s * (STAGE_F * 4)
                              + (uint32_t)tile * (64 * PSTR * 4)
                              + (uint32_t)r * (PSTR * 4) + (uint32_t)c4 * 16;
            const float* src = tile
                ? Vh + (size_t)r * SEQ + (size_t)kt2 * 64 + c4 * 4     // r = d
                : Kh + ((size_t)kt2 * 64 + r) * HD + c4 * 4;           // r = key
            cp16(dst, src);
        }
        CP_COMMIT();
    };

    load_stage(0, 0);
    load_stage(1, 1);

    // Stage 128 Q rows through the (not yet filled) stage-2 buffer (fits exactly)
    float* Qs = sm + 2 * STAGE_F;
    {
        const float* Qg = g_q + ((size_t)h * SEQ + (size_t)qt * 128) * HD;
#pragma unroll
        for (int i = 0; i < 8; i++) {
            int id = t + i * 256;              // float4 units, 0..2047
            int r  = id >> 4;                  // 0..127
            int c  = (id & 15) * 4;
            *(float4*)&Qs[r * PSTR + c] = *(const float4*)&Qg[(size_t)r * HD + c];
        }
    }
    __syncthreads();
    float qf[8][4];
#pragma unroll
    for (int k = 0; k < 8; k++) {
        float2 a0 = *(const float2*)&Qs[(w16 + lr) * PSTR + k * 8 + 2 * lc];
        float2 a1 = *(const float2*)&Qs[(w16 + lr + 8) * PSTR + k * 8 + 2 * lc];
        qf[k][0] = a0.x; qf[k][2] = a0.y;
        qf[k][1] = a1.x; qf[k][3] = a1.y;
    }
    // iter-0's loop-top barrier orders these reads before stage-2's first fill

    float ob[8][4];
#pragma unroll
    for (int j = 0; j < 8; j++)
#pragma unroll
        for (int i = 0; i < 4; i++) ob[j][i] = 0.f;
    float accl[4] = {0.f, 0.f, 0.f, 0.f};
    const float bl = (lr == 0) ? 1.f : 0.f;
    float m0 = -1e30f, m1 = -1e30f;

    for (int kt = 0; kt < SEQ / 64; kt++) {
        const int s = kt % 3;
        const float* Ks = sm + s * STAGE_F;
        const float* Vs = Ks + 64 * PSTR;

        CP_WAITG1();          // tile kt resident
        __syncthreads();      // all warps past iter kt-1 (stage (kt+2)%3 free)

        if (kt + 2 < SEQ / 64) load_stage(kt + 2, (kt + 2) % 3);
        else CP_COMMIT();

        // ---- S = Q * K^T ----
        float sc[8][4];
#pragma unroll
        for (int j = 0; j < 8; j++)
#pragma unroll
            for (int i = 0; i < 4; i++) sc[j][i] = 0.f;
#pragma unroll
        for (int k = 0; k < 8; k++) {
#pragma unroll
            for (int j = 0; j < 8; j++) {
                float2 b = *(const float2*)&Ks[(j * 8 + lr) * PSTR + k * 8 + 2 * lc];
                mma_tf32(sc[j], qf[k], b.x, b.y);
            }
        }

        // ---- online softmax, P stays in registers ----
        float mx0 = sc[0][0], mx1 = sc[0][2];
#pragma unroll
        for (int j = 0; j < 8; j++) {
            mx0 = fmaxf(mx0, fmaxf(sc[j][0], sc[j][1]));
            mx1 = fmaxf(mx1, fmaxf(sc[j][2], sc[j][3]));
        }
        mx0 = fmaxf(mx0, __shfl_xor_sync(0xffffffffu, mx0, 1));
        mx0 = fmaxf(mx0, __shfl_xor_sync(0xffffffffu, mx0, 2));
        mx1 = fmaxf(mx1, __shfl_xor_sync(0xffffffffu, mx1, 1));
        mx1 = fmaxf(mx1, __shfl_xor_sync(0xffffffffu, mx1, 2));
        float nm0 = fmaxf(m0, mx0), nm1 = fmaxf(m1, mx1);
        float corr0 = ex2f((m0 - nm0) * LOG2E);
        float corr1 = ex2f((m1 - nm1) * LOG2E);
#pragma unroll
        for (int j = 0; j < 8; j++) {
            sc[j][0] = ex2f((sc[j][0] - nm0) * LOG2E);
            sc[j][1] = ex2f((sc[j][1] - nm0) * LOG2E);
            sc[j][2] = ex2f((sc[j][2] - nm1) * LOG2E);
            sc[j][3] = ex2f((sc[j][3] - nm1) * LOG2E);
        }
        m0 = nm0; m1 = nm1;
#pragma unroll
        for (int j = 0; j < 8; j++) {
            ob[j][0] *= corr0; ob[j][1] *= corr0;
            ob[j][2] *= corr1; ob[j][3] *= corr1;
        }
        accl[0] *= corr0; accl[2] *= corr1;

        // ---- O += P*V ; l += P*1 ----
#pragma unroll
        for (int k = 0; k < 8; k++) {
            float pf[4];
            pf[0] = sc[k][0];
            pf[1] = sc[k][2];
            pf[2] = sc[k][1];
            pf[3] = sc[k][3];
#pragma unroll
            for (int j = 0; j < 8; j++) {
                float2 b = *(const float2*)&Vs[(j * 8 + lr) * PSTR + k * 8 + 2 * lc];
                mma_tf32(ob[j], pf, b.x, b.y);
            }
            mma_tf32(accl, pf, bl, bl);
        }
        // next iter's loop-top barrier covers stage reuse
    }

    float l0 = __shfl_sync(0xffffffffu, accl[0], lane & 28);
    float l1 = __shfl_sync(0xffffffffu, accl[2], lane & 28);
    float inv0 = 1.f / l0, inv1 = 1.f / l1;
    float* d0 = g_att + ((size_t)qt * 128 + w16 + lr) * DIM + h * HD;
    float* d1 = d0 + 8 * DIM;
#pragma unroll
    for (int j = 0; j < 8; j++) {
        *(float2*)&d0[j * 8 + lc * 2] =
            make_float2(tf32_rna(ob[j][0] * inv0), tf32_rna(ob[j][1] * inv0));
        *(float2*)&d1[j * 8 + lc * 2] =
            make_float2(tf32_rna(ob[j][2] * inv1), tf32_rna(ob[j][3] * inv1));
    }
}

// ---------------------------------------------------------------------------
extern "C" void kernel_launch(void* const* d_in, const int* in_sizes, int n_in,
                              void* d_out, int out_size) {
    const float* x     = (const float*)d_in[0];
    const float* Wqkv  = (const float*)d_in[1];
    const float* bqkv  = (const float*)d_in[2];
    const float* Wproj = (const float*)d_in[3];
    const float* bproj = (const float*)d_in[4];
    float* out = (float*)d_out;

    const int gemm_shm = 3 * STG_F * (int)sizeof(float);        // 62976 B
    const int attn_shm = ATTN_SM_F * (int)sizeof(float);        // 110592 B

    // 0) pre-round x / W_qkv / W_proj to tf32
    pre_round<<<(int)((TOT4 + 255) / 256), 256>>>(x, Wqkv, Wproj);

    // 1) QKV projection (tf32 MMA, 3-stage pipeline)
    cudaFuncSetAttribute(gemm_tc<3 * DIM, 0>, cudaFuncAttributeMaxDynamicSharedMemorySize, gemm_shm);
    gemm_tc<3 * DIM, 0><<<dim3(24, 32), 256, gemm_shm>>>(bqkv, nullptr);

    // 2) warp-MMA tf32 flash attention (256 threads, 128 q-rows/block)
    cudaFuncSetAttribute(attn_mma, cudaFuncAttributeMaxDynamicSharedMemorySize, attn_shm);
    attn_mma<<<dim3(SEQ / 128, NH), 256, attn_shm>>>();

    // 3) Output projection (tf32 MMA, 3-stage pipeline)
    cudaFuncSetAttribute(gemm_tc<DIM, 1>, cudaFuncAttributeMaxDynamicSharedMemorySize, gemm_shm);
    gemm_tc<DIM, 1><<<dim3(8, 32), 256, gemm_shm>>>(bproj, out);
}

// round 12
// speedup vs baseline: 1.2669x; 1.2372x over previous
#include <cuda_runtime.h>
#include <cuda_fp16.h>
#include <cstdint>

#define SEQ  4096
#define DIM  1024
#define NH   16
#define HD   64

// Scratch (allocation-free rule: __device__ globals)
__device__ __half g_q[(size_t)NH * SEQ * HD];  // [H][SEQ][HD] fp16, x0.125, d pair-permuted
__device__ __half g_k[(size_t)NH * SEQ * HD];  // [H][SEQ][HD] fp16, d pair-permuted
__device__ __half g_v[(size_t)NH * HD * SEQ];  // [H][HD][SEQ] fp16 (d-major), seq pair-permuted
__device__ float  g_att[(size_t)SEQ * DIM];    // tf32 (attn epilogue)
__device__ float  g_x [(size_t)SEQ * DIM];
__device__ float  g_wq[(size_t)DIM * 3 * DIM];
__device__ float  g_wp[(size_t)DIM * DIM];

// ---------------------------------------------------------------------------
__device__ __forceinline__ uint32_t smem_u32(const void* p) {
    uint32_t a;
    asm("{ .reg .u64 t; cvta.to.shared.u64 t, %1; cvt.u32.u64 %0, t; }" : "=r"(a) : "l"(p));
    return a;
}
__device__ __forceinline__ float ex2f(float x) {
    float r; asm("ex2.approx.ftz.f32 %0, %1;" : "=f"(r) : "f"(x)); return r;
}
__device__ __forceinline__ float tf32_rna(float x) {
    uint32_t u; asm("cvt.rna.tf32.f32 %0, %1;" : "=r"(u) : "f"(x)); return __uint_as_float(u);
}
__device__ __forceinline__ void cp16(uint32_t dst, const void* src) {
    asm volatile("cp.async.cg.shared.global [%0], [%1], 16;" :: "r"(dst), "l"(src));
}
#define CP_COMMIT() asm volatile("cp.async.commit_group;" ::: "memory")
#define CP_WAITG1() asm volatile("cp.async.wait_group 1;" ::: "memory")

__device__ __forceinline__ void mma_tf32(float* d, const float* a, float b0, float b1) {
    asm volatile(
        "mma.sync.aligned.m16n8k8.row.col.f32.tf32.tf32.f32 "
        "{%0,%1,%2,%3}, {%4,%5,%6,%7}, {%8,%9}, {%0,%1,%2,%3};"
        : "+f"(d[0]), "+f"(d[1]), "+f"(d[2]), "+f"(d[3])
        : "r"(__float_as_uint(a[0])), "r"(__float_as_uint(a[1])),
          "r"(__float_as_uint(a[2])), "r"(__float_as_uint(a[3])),
          "r"(__float_as_uint(b0)), "r"(__float_as_uint(b1)));
}

__device__ __forceinline__ void mma_f16(float* d, const uint32_t* a, uint32_t b0, uint32_t b1) {
    asm volatile(
        "mma.sync.aligned.m16n8k16.row.col.f32.f16.f16.f32 "
        "{%0,%1,%2,%3}, {%4,%5,%6,%7}, {%8,%9}, {%0,%1,%2,%3};"
        : "+f"(d[0]), "+f"(d[1]), "+f"(d[2]), "+f"(d[3])
        : "r"(a[0]), "r"(a[1]), "r"(a[2]), "r"(a[3]), "r"(b0), "r"(b1));
}

__device__ __forceinline__ uint32_t pack2(float x, float y) {
    __half2 h = __floats2half2_rn(x, y);
    return *(uint32_t*)&h;
}

// Pair-interleave permutation within 16-element groups:
// natural i -> phys so that phys 4-element unit u = naturals {2u,2u+1,2u+8,2u+9}.
__device__ __forceinline__ int pidx(int i) {
    int p = (i & 15) >> 1, o = i & 1;
    int pp = (p < 4) ? 2 * p : 2 * (p - 4) + 1;
    return (i & ~15) | (pp * 2 + o);
}

#define LOG2E 1.44269504f

// ---------------------------------------------------------------------------
// Pre-round x / W_qkv / W_proj to tf32 (RNA) once per launch.
// ---------------------------------------------------------------------------
#define XN   ((size_t)SEQ * DIM)
#define WQN  ((size_t)DIM * 3 * DIM)
#define WPN  ((size_t)DIM * DIM)
#define TOT4 ((XN + WQN + WPN) / 4)

__global__ __launch_bounds__(256) void pre_round(const float* __restrict__ x,
                                                 const float* __restrict__ wq,
                                                 const float* __restrict__ wp) {
    size_t i = (size_t)blockIdx.x * blockDim.x + threadIdx.x;
    if (i >= TOT4) return;
    const float* src;
    float* dst;
    size_t off;
    if (i < XN / 4)                { src = x;  dst = g_x;  off = i; }
    else if (i < (XN + WQN) / 4)   { src = wq; dst = g_wq; off = i - XN / 4; }
    else                           { src = wp; dst = g_wp; off = i - (XN + WQN) / 4; }
    float4 v = ((const float4*)src)[off];
    v.x = tf32_rna(v.x); v.y = tf32_rna(v.y);
    v.z = tf32_rna(v.z); v.w = tf32_rna(v.w);
    ((float4*)dst)[off] = v;
}

// ---------------------------------------------------------------------------
// tf32 warp-MMA GEMM, 3-stage pipeline (round-9 body).
// MODE 0 epilogue emits fp16 q/k/v with pair-interleave permutation.
// ---------------------------------------------------------------------------
#define ASTR 24
#define BSTR 136
#define A_ST_F (128 * ASTR)
#define B_ST_F (16 * BSTR)
#define STG_F  (A_ST_F + B_ST_F)       // 5248 floats / stage
#define NCHUNK (DIM / 16)              // 64

template <int N_, int MODE>
__global__ __launch_bounds__(256) void gemm_tc(const float* __restrict__ bias,
                                               float* __restrict__ C) {
    extern __shared__ float sm[];
    const uint32_t sb = smem_u32(sm);
    const int K = DIM;
    const float* A = (MODE == 1) ? g_att : g_x;
    const float* B = (MODE == 1) ? g_wp : g_wq;

    const int t    = threadIdx.x;
    const int w    = t >> 5;
    const int lane = t & 31;
    const int lr   = lane >> 2;
    const int lc   = lane & 3;
    const int wm   = (w >> 2) * 64;
    const int wn   = (w & 3) * 32;
    const int rowBase = blockIdx.y * 128;
    const int colBase = blockIdx.x * 128;

    auto load_chunk = [&](int k0, int s) {
        uint32_t base = sb + (uint32_t)s * (STG_F * 4);
#pragma unroll
        for (int i = 0; i < 2; i++) {
            int id = t + i * 256;
            int r  = id >> 2;
            int c4 = id & 3;
            cp16(base + (uint32_t)r * (ASTR * 4) + (uint32_t)c4 * 16,
                 A + (size_t)(rowBase + r) * K + k0 + c4 * 4);
        }
#pragma unroll
        for (int i = 0; i < 2; i++) {
            int id = t + i * 256;
            int r  = id >> 5;
            int c4 = id & 31;
            int j  = r & 7;
            int rs = (r & 8) + ((j & 1) ? (j >> 1) + 4 : (j >> 1));
            cp16(base + (uint32_t)(A_ST_F * 4) + (uint32_t)rs * (BSTR * 4) + (uint32_t)c4 * 16,
                 B + (size_t)(k0 + r) * N_ + colBase + c4 * 4);
        }
        CP_COMMIT();
    };

    load_chunk(0, 0);
    load_chunk(16, 1);

    float acc[4][4][4];
#pragma unroll
    for (int mt = 0; mt < 4; mt++)
#pragma unroll
        for (int nt = 0; nt < 4; nt++)
#pragma unroll
            for (int i = 0; i < 4; i++) acc[mt][nt][i] = 0.f;

    for (int kc = 0; kc < NCHUNK; kc++) {
        const int s = kc % 3;
        const float* As = sm + s * STG_F;
        const float* Bs = As + A_ST_F;

        CP_WAITG1();
        __syncthreads();

        if (kc + 2 < NCHUNK) load_chunk((kc + 2) * 16, (kc + 2) % 3);
        else CP_COMMIT();

#pragma unroll
        for (int kk = 0; kk < 2; kk++) {
            const int k = kk * 8;
            float af[4][4];
#pragma unroll
            for (int mt = 0; mt < 4; mt++) {
                int mb = wm + mt * 16;
                float2 a0 = *(const float2*)&As[(mb + lr) * ASTR + k + 2 * lc];
                float2 a1 = *(const float2*)&As[(mb + lr + 8) * ASTR + k + 2 * lc];
                af[mt][0] = a0.x; af[mt][2] = a0.y;
                af[mt][1] = a1.x; af[mt][3] = a1.y;
            }
            float bf[4][2];
#pragma unroll
            for (int nt = 0; nt < 4; nt++) {
                int n = wn + nt * 8 + lr;
                bf[nt][0] = Bs[(k + lc) * BSTR + n];
                bf[nt][1] = Bs[(k + lc + 4) * BSTR + n];
            }
#pragma unroll
            for (int mt = 0; mt < 4; mt++)
#pragma unroll
                for (int nt = 0; nt < 4; nt++)
                    mma_tf32(acc[mt][nt], af[mt], bf[nt][0], bf[nt][1]);
        }
    }

    // Epilogue
#pragma unroll
    for (int nt = 0; nt < 4; nt++) {
        int c = colBase + wn + nt * 8 + 2 * lc;
        float2 bv = *(const float2*)&bias[c];
#pragma unroll
        for (int mt = 0; mt < 4; mt++) {
            int r0 = rowBase + wm + mt * 16 + lr;
            int r1 = r0 + 8;
            float v00 = acc[mt][nt][0] + bv.x, v01 = acc[mt][nt][1] + bv.y;
            float v10 = acc[mt][nt][2] + bv.x, v11 = acc[mt][nt][3] + bv.y;
            if (MODE == 0) {
                int which = c >> 10;
                int c2    = c & 1023;
                int head  = c2 >> 6;
                int d     = c2 & 63;
                if (which == 0) {
                    __half* dq = g_q + ((size_t)head * SEQ) * HD + pidx(d);
                    *(__half2*)&dq[(size_t)r0 * HD] = __floats2half2_rn(v00 * 0.125f, v01 * 0.125f);
                    *(__half2*)&dq[(size_t)r1 * HD] = __floats2half2_rn(v10 * 0.125f, v11 * 0.125f);
                } else if (which == 1) {
                    __half* dk = g_k + ((size_t)head * SEQ) * HD + pidx(d);
                    *(__half2*)&dk[(size_t)r0 * HD] = __floats2half2_rn(v00, v01);
                    *(__half2*)&dk[(size_t)r1 * HD] = __floats2half2_rn(v10, v11);
                } else {
                    // v: d-major [H][HD][SEQ], seq index pair-permuted
                    __half* dv = g_v + (size_t)head * HD * SEQ;
                    int p0 = pidx(r0), p1 = pidx(r1);
                    dv[(size_t)(d)     * SEQ + p0] = __float2half_rn(v00);
                    dv[(size_t)(d + 1) * SEQ + p0] = __float2half_rn(v01);
                    dv[(size_t)(d)     * SEQ + p1] = __float2half_rn(v10);
                    dv[(size_t)(d + 1) * SEQ + p1] = __float2half_rn(v11);
                }
            } else {
                *(float2*)&C[(size_t)r0 * N_ + c] = make_float2(v00, v01);
                *(float2*)&C[(size_t)r1 * N_ + c] = make_float2(v10, v11);
            }
        }
    }
}

// ---------------------------------------------------------------------------
// fp16 warp-MMA flash attention (m16n8k16, f32 accum). Register-resident P,
// 3-stage KV pipeline, 1 barrier/iter. Block = 64 q-rows x head, 128 threads.
// K tile [64 key][72 half] (d permuted), V tile [64 d][72] (key permuted).
// Stage = 18432 B; 3 stages = 55296 B -> up to 4 blocks/SM.
// ---------------------------------------------------------------------------
#define HSTR 72
#define STAGE_H (2 * 64 * HSTR)        // 9216 halves per stage (K+V)
#define STAGE_B (STAGE_H * 2)          // 18432 bytes
#define ATTN_SM_B (3 * STAGE_B)        // 55296 bytes

__global__ __launch_bounds__(128) void attn_mma() {
    extern __shared__ __half smh[];
    const uint32_t sb = smem_u32(smh);

    const int t    = threadIdx.x;
    const int lane = t & 31;
    const int lr   = lane >> 2;
    const int lc   = lane & 3;
    const int w16  = (t >> 5) * 16;
    const int h  = blockIdx.y;
    const int qt = blockIdx.x;

    const __half* Kh = g_k + (size_t)h * SEQ * HD;   // [key][d-permuted]
    const __half* Vh = g_v + (size_t)h * HD * SEQ;   // [d][key-permuted]

    auto load_stage = [&](int kt2, int s) {
#pragma unroll
        for (int i = 0; i < 8; i++) {
            int id   = t + i * 128;            // 0..1023 (16B units)
            int tile = id >> 9;                // 0=K 1=V
            int r    = (id >> 3) & 63;
            int c4   = id & 7;                 // 8 halves per unit
            uint32_t dst = sb + (uint32_t)s * STAGE_B
                              + (uint32_t)tile * (64 * HSTR * 2)
                              + (uint32_t)r * (HSTR * 2) + (uint32_t)c4 * 16;
            const __half* src = tile
                ? Vh + (size_t)r * SEQ + (size_t)kt2 * 64 + c4 * 8     // r = d
                : Kh + ((size_t)kt2 * 64 + r) * HD + c4 * 8;           // r = key
            cp16(dst, src);
        }
        CP_COMMIT();
    };

    load_stage(0, 0);
    load_stage(1, 1);

    // Stage 64 Q rows through the (not yet filled) stage-2 buffer
    __half* Qs = smh + 2 * STAGE_H;
    {
        const __half* Qg = g_q + ((size_t)h * SEQ + (size_t)qt * 64) * HD;
#pragma unroll
        for (int i = 0; i < 4; i++) {
            int id = t + i * 128;              // 16B units, 0..511
            int r  = id >> 3;
            int c4 = id & 7;
            *(float4*)&Qs[r * HSTR + c4 * 8] = *(const float4*)&Qg[(size_t)r * HD + c4 * 8];
        }
    }
    __syncthreads();
    uint32_t qf[4][4];
#pragma unroll
    for (int G = 0; G < 4; G++) {
        uint2 a02 = *(const uint2*)&Qs[(w16 + lr) * HSTR + G * 16 + lc * 4];
        uint2 a13 = *(const uint2*)&Qs[(w16 + lr + 8) * HSTR + G * 16 + lc * 4];
        qf[G][0] = a02.x; qf[G][2] = a02.y;
        qf[G][1] = a13.x; qf[G][3] = a13.y;
    }
    // iter-0's loop-top barrier orders these reads before stage-2's first fill

    float ob[8][4];
#pragma unroll
    for (int j = 0; j < 8; j++)
#pragma unroll
        for (int i = 0; i < 4; i++) ob[j][i] = 0.f;
    float accl[4] = {0.f, 0.f, 0.f, 0.f};
    const uint32_t bl2 = (lr == 0) ? 0x3C003C00u : 0u;   // half2(1,1) / 0
    float m0 = -1e30f, m1 = -1e30f;

    for (int kt = 0; kt < SEQ / 64; kt++) {
        const int s = kt % 3;
        const __half* Ks = smh + s * STAGE_H;
        const __half* Vs = Ks + 64 * HSTR;

        CP_WAITG1();          // tile kt resident
        __syncthreads();      // all warps past iter kt-1

        if (kt + 2 < SEQ / 64) load_stage(kt + 2, (kt + 2) % 3);
        else CP_COMMIT();

        // ---- S = Q * K^T  (fp16 k16) ----
        float sc[8][4];
#pragma unroll
        for (int j = 0; j < 8; j++)
#pragma unroll
            for (int i = 0; i < 4; i++) sc[j][i] = 0.f;
#pragma unroll
        for (int G = 0; G < 4; G++) {
#pragma unroll
            for (int j = 0; j < 8; j++) {
                uint2 b = *(const uint2*)&Ks[(j * 8 + lr) * HSTR + G * 16 + lc * 4];
                mma_f16(sc[j], qf[G], b.x, b.y);
            }
        }

        // ---- online softmax, P stays in registers ----
        float mx0 = sc[0][0], mx1 = sc[0][2];
#pragma unroll
        for (int j = 0; j < 8; j++) {
            mx0 = fmaxf(mx0, fmaxf(sc[j][0], sc[j][1]));
            mx1 = fmaxf(mx1, fmaxf(sc[j][2], sc[j][3]));
        }
        mx0 = fmaxf(mx0, __shfl_xor_sync(0xffffffffu, mx0, 1));
        mx0 = fmaxf(mx0, __shfl_xor_sync(0xffffffffu, mx0, 2));
        mx1 = fmaxf(mx1, __shfl_xor_sync(0xffffffffu, mx1, 1));
        mx1 = fmaxf(mx1, __shfl_xor_sync(0xffffffffu, mx1, 2));
        float nm0 = fmaxf(m0, mx0), nm1 = fmaxf(m1, mx1);
        float corr0 = ex2f((m0 - nm0) * LOG2E);
        float corr1 = ex2f((m1 - nm1) * LOG2E);
#pragma unroll
        for (int j = 0; j < 8; j++) {
            sc[j][0] = ex2f((sc[j][0] - nm0) * LOG2E);
            sc[j][1] = ex2f((sc[j][1] - nm0) * LOG2E);
            sc[j][2] = ex2f((sc[j][2] - nm1) * LOG2E);
            sc[j][3] = ex2f((sc[j][3] - nm1) * LOG2E);
        }
        m0 = nm0; m1 = nm1;
#pragma unroll
        for (int j = 0; j < 8; j++) {
            ob[j][0] *= corr0; ob[j][1] *= corr0;
            ob[j][2] *= corr1; ob[j][3] *= corr1;
        }
        accl[0] *= corr0; accl[2] *= corr1;

        // ---- O += P*V ; l += P*1  (P packed from sc, k16 over keys) ----
#pragma unroll
        for (int J = 0; J < 4; J++) {
            uint32_t pf[4];
            pf[0] = pack2(sc[2 * J][0],     sc[2 * J][1]);
            pf[1] = pack2(sc[2 * J][2],     sc[2 * J][3]);
            pf[2] = pack2(sc[2 * J + 1][0], sc[2 * J + 1][1]);
            pf[3] = pack2(sc[2 * J + 1][2], sc[2 * J + 1][3]);
#pragma unroll
            for (int j = 0; j < 8; j++) {
                uint2 b = *(const uint2*)&Vs[(j * 8 + lr) * HSTR + J * 16 + lc * 4];
                mma_f16(ob[j], pf, b.x, b.y);
            }
            mma_f16(accl, pf, bl2, bl2);
        }
        // next iter's loop-top barrier covers stage reuse
    }

    float l0 = __shfl_sync(0xffffffffu, accl[0], lane & 28);
    float l1 = __shfl_sync(0xffffffffu, accl[2], lane & 28);
    float inv0 = 1.f / l0, inv1 = 1.f / l1;
    float* d0 = g_att + ((size_t)qt * 64 + w16 + lr) * DIM + h * HD;
    float* d1 = d0 + 8 * DIM;
#pragma unroll
    for (int j = 0; j < 8; j++) {
        *(float2*)&d0[j * 8 + lc * 2] =
            make_float2(tf32_rna(ob[j][0] * inv0), tf32_rna(ob[j][1] * inv0));
        *(float2*)&d1[j * 8 + lc * 2] =
            make_float2(tf32_rna(ob[j][2] * inv1), tf32_rna(ob[j][3] * inv1));
    }
}

// ---------------------------------------------------------------------------
extern "C" void kernel_launch(void* const* d_in, const int* in_sizes, int n_in,
                              void* d_out, int out_size) {
    const float* x     = (const float*)d_in[0];
    const float* Wqkv  = (const float*)d_in[1];
    const float* bqkv  = (const float*)d_in[2];
    const float* Wproj = (const float*)d_in[3];
    const float* bproj = (const float*)d_in[4];
    float* out = (float*)d_out;

    const int gemm_shm = 3 * STG_F * (int)sizeof(float);   // 62976 B
    const int attn_shm = ATTN_SM_B;                        // 55296 B

    // 0) pre-round x / W_qkv / W_proj to tf32
    pre_round<<<(int)((TOT4 + 255) / 256), 256>>>(x, Wqkv, Wproj);

    // 1) QKV projection (tf32 MMA) -> fp16 q (scaled), k, v (permuted layouts)
    cudaFuncSetAttribute(gemm_tc<3 * DIM, 0>, cudaFuncAttributeMaxDynamicSharedMemorySize, gemm_shm);
    gemm_tc<3 * DIM, 0><<<dim3(24, 32), 256, gemm_shm>>>(bqkv, nullptr);

    // 2) fp16 warp-MMA flash attention
    cudaFuncSetAttribute(attn_mma, cudaFuncAttributeMaxDynamicSharedMemorySize, attn_shm);
    attn_mma<<<dim3(SEQ / 64, NH), 128, attn_shm>>>();

    // 3) Output projection (tf32 MMA)
    cudaFuncSetAttribute(gemm_tc<DIM, 1>, cudaFuncAttributeMaxDynamicSharedMemorySize, gemm_shm);
    gemm_tc<DIM, 1><<<dim3(8, 32), 256, gemm_shm>>>(bproj, out);
}

// round 14
// speedup vs baseline: 1.5221x; 1.2015x over previous
#include <cuda_runtime.h>
#include <cuda_fp16.h>
#include <cstdint>

#define SEQ  4096
#define DIM  1024
#define NH   16
#define HD   64

// Scratch (allocation-free rule: __device__ globals)
__device__ __half  g_q[(size_t)NH * SEQ * HD];   // [H][SEQ][HD] fp16, x0.125, d pair-permuted
__device__ __half  g_k[(size_t)NH * SEQ * HD];   // [H][SEQ][HD] fp16, d pair-permuted
__device__ __half  g_v[(size_t)NH * HD * SEQ];   // [H][HD][SEQ] fp16 (d-major), seq pair-permuted
__device__ __half  g_att[(size_t)SEQ * DIM];     // fp16, k pair-permuted (proj A operand)
__device__ __half  g_xh[(size_t)SEQ * DIM];      // fp16 x, k pair-permuted
__device__ __half2 g_wqp[(size_t)(DIM / 2) * 3 * DIM]; // W_qkv k-pair-packed [K/2][3N]
__device__ __half2 g_wpp[(size_t)(DIM / 2) * DIM];     // W_proj k-pair-packed

// ---------------------------------------------------------------------------
__device__ __forceinline__ uint32_t smem_u32(const void* p) {
    uint32_t a;
    asm("{ .reg .u64 t; cvta.to.shared.u64 t, %1; cvt.u32.u64 %0, t; }" : "=r"(a) : "l"(p));
    return a;
}
__device__ __forceinline__ float ex2f(float x) {
    float r; asm("ex2.approx.ftz.f32 %0, %1;" : "=f"(r) : "f"(x)); return r;
}
__device__ __forceinline__ void cp16(uint32_t dst, const void* src) {
    asm volatile("cp.async.cg.shared.global [%0], [%1], 16;" :: "r"(dst), "l"(src));
}
#define CP_COMMIT() asm volatile("cp.async.commit_group;" ::: "memory")
#define CP_WAITG1() asm volatile("cp.async.wait_group 1;" ::: "memory")

__device__ __forceinline__ void mma_f16(float* d, const uint32_t* a, uint32_t b0, uint32_t b1) {
    asm volatile(
        "mma.sync.aligned.m16n8k16.row.col.f32.f16.f16.f32 "
        "{%0,%1,%2,%3}, {%4,%5,%6,%7}, {%8,%9}, {%0,%1,%2,%3};"
        : "+f"(d[0]), "+f"(d[1]), "+f"(d[2]), "+f"(d[3])
        : "r"(a[0]), "r"(a[1]), "r"(a[2]), "r"(a[3]), "r"(b0), "r"(b1));
}

__device__ __forceinline__ uint32_t pack2(float x, float y) {
    __half2 h = __floats2half2_rn(x, y);
    return *(uint32_t*)&h;
}

// Pair permutation within 16-groups: natural pair p (0..7) -> phys pair.
__device__ __forceinline__ int ppair(int p) { return (p < 4) ? 2 * p : 2 * p - 7; }
// Natural element index -> phys element index.
__device__ __forceinline__ int pidx(int i) {
    int p = (i & 15) >> 1;
    return (i & ~15) | (ppair(p) * 2 + (i & 1));
}

#define LOG2E 1.44269504f

// ---------------------------------------------------------------------------
// Pack inputs to fp16 attention/GEMM layouts:
//  x -> g_xh (pidx-permuted cols), W -> k-pair-packed half2 [K/2][N].
// ---------------------------------------------------------------------------
#define XT  ((size_t)SEQ * DIM / 4)             // 1048576 threads (4 cols each)
#define WQT ((size_t)(DIM / 2) * 3 * DIM / 4)   // 393216
#define WPT ((size_t)(DIM / 2) * DIM / 4)       // 131072
#define PACK_T (XT + WQT + WPT)

__global__ __launch_bounds__(256) void pack_inputs(const float* __restrict__ x,
                                                   const float* __restrict__ wq,
                                                   const float* __restrict__ wp) {
    size_t i = (size_t)blockIdx.x * blockDim.x + threadIdx.x;
    if (i >= PACK_T) return;
    if (i < XT) {
        int row = (int)(i >> 8);               // DIM/4 = 256 per row
        int c   = ((int)i & 255) << 2;
        float4 v = *(const float4*)&x[(size_t)row * DIM + c];
        int pl = (c & 15) >> 1;                // 0,2,4,6
        __half2* dst = (__half2*)g_xh + ((size_t)row * DIM + (c & ~15)) / 2;
        dst[ppair(pl)]     = __floats2half2_rn(v.x, v.y);
        dst[ppair(pl + 1)] = __floats2half2_rn(v.z, v.w);
    } else if (i < XT + WQT) {
        size_t j = i - XT;
        int p = (int)(j / 768);
        int c = ((int)(j % 768)) * 4;
        float4 a = *(const float4*)&wq[(size_t)(2 * p) * (3 * DIM) + c];
        float4 b = *(const float4*)&wq[(size_t)(2 * p + 1) * (3 * DIM) + c];
        __half2* dst = g_wqp + (size_t)p * (3 * DIM) + c;
        dst[0] = __floats2half2_rn(a.x, b.x);
        dst[1] = __floats2half2_rn(a.y, b.y);
        dst[2] = __floats2half2_rn(a.z, b.z);
        dst[3] = __floats2half2_rn(a.w, b.w);
    } else {
        size_t j = i - XT - WQT;
        int p = (int)(j >> 8);
        int c = ((int)j & 255) * 4;
        float4 a = *(const float4*)&wp[(size_t)(2 * p) * DIM + c];
        float4 b = *(const float4*)&wp[(size_t)(2 * p + 1) * DIM + c];
        __half2* dst = g_wpp + (size_t)p * DIM + c;
        dst[0] = __floats2half2_rn(a.x, b.x);
        dst[1] = __floats2half2_rn(a.y, b.y);
        dst[2] = __floats2half2_rn(a.z, b.z);
        dst[3] = __floats2half2_rn(a.w, b.w);
    }
}

// ---------------------------------------------------------------------------
// fp16 warp-MMA GEMM (m16n8k16), 3-stage / 1-barrier pipeline.
// Block 128x128, 8 warps (2x4), warp tile 64x32, k-chunk 16.
// A smem [128][24] halves (pidx-permuted k); B smem [8 pairs][136] half2.
// MODE 0: g_xh x g_wqp -> fp16 q(x0.125)/k/v (permuted). MODE 1: g_att x g_wpp -> fp32 C.
// ---------------------------------------------------------------------------
#define ASTRH 24
#define BSTRH 136                       // half2 stride (8 mod 32 words: conflict-free)
#define A_ST_B (128 * ASTRH * 2)        // 6144 bytes
#define B_ST_B (8 * BSTRH * 4)          // 4352 bytes
#define GSTG_B (A_ST_B + B_ST_B)        // 10496 bytes / stage
#define NCHUNK (DIM / 16)               // 64

template <int N_, int MODE>
__global__ __launch_bounds__(256) void gemm_tc(const float* __restrict__ bias,
                                               float* __restrict__ C) {
    extern __shared__ char smc[];
    const uint32_t sb = smem_u32(smc);
    const __half*  A  = (MODE == 1) ? g_att : g_xh;
    const __half2* Bp = (MODE == 1) ? g_wpp : g_wqp;

    const int t    = threadIdx.x;
    const int w    = t >> 5;
    const int lane = t & 31;
    const int lr   = lane >> 2;
    const int lc   = lane & 3;
    const int wm   = (w >> 2) * 64;
    const int wn   = (w & 3) * 32;
    const int rowBase = blockIdx.y * 128;
    const int colBase = blockIdx.x * 128;

    auto load_chunk = [&](int k0, int s) {
        uint32_t base = sb + (uint32_t)s * GSTG_B;
        {   // A: 128 rows x 2 16B-units (16 halves/row)
            int r = t >> 1, u = t & 1;
            cp16(base + (uint32_t)r * (ASTRH * 2) + (uint32_t)u * 16,
                 A + (size_t)(rowBase + r) * DIM + k0 + u * 8);
        }
        {   // B: 8 pair-rows x 32 16B-units (128 half2/row)
            int pr = t >> 5, c4 = t & 31;
            cp16(base + A_ST_B + (uint32_t)pr * (BSTRH * 4) + (uint32_t)c4 * 16,
                 Bp + (size_t)(k0 / 2 + pr) * N_ + colBase + c4 * 4);
        }
        CP_COMMIT();
    };

    load_chunk(0, 0);
    load_chunk(16, 1);

    float acc[4][4][4];
#pragma unroll
    for (int mt = 0; mt < 4; mt++)
#pragma unroll
        for (int nt = 0; nt < 4; nt++)
#pragma unroll
            for (int i = 0; i < 4; i++) acc[mt][nt][i] = 0.f;

    for (int kc = 0; kc < NCHUNK; kc++) {
        const int s = kc % 3;
        const __half*  As = (const __half*)(smc + (size_t)s * GSTG_B);
        const __half2* Bs = (const __half2*)(smc + (size_t)s * GSTG_B + A_ST_B);

        CP_WAITG1();
        __syncthreads();

        if (kc + 2 < NCHUNK) load_chunk((kc + 2) * 16, (kc + 2) % 3);
        else CP_COMMIT();

        uint32_t af[4][4];
#pragma unroll
        for (int mt = 0; mt < 4; mt++) {
            int mb = wm + mt * 16;
            uint2 a0 = *(const uint2*)&As[(mb + lr) * ASTRH + lc * 4];
            uint2 a1 = *(const uint2*)&As[(mb + lr + 8) * ASTRH + lc * 4];
            af[mt][0] = a0.x; af[mt][1] = a1.x;
            af[mt][2] = a0.y; af[mt][3] = a1.y;
        }
        uint32_t bf[4][2];
#pragma unroll
        for (int nt = 0; nt < 4; nt++) {
            int n = wn + nt * 8 + lr;
            bf[nt][0] = *(const uint32_t*)&Bs[lc * BSTRH + n];
            bf[nt][1] = *(const uint32_t*)&Bs[(lc + 4) * BSTRH + n];
        }
#pragma unroll
        for (int mt = 0; mt < 4; mt++)
#pragma unroll
            for (int nt = 0; nt < 4; nt++)
                mma_f16(acc[mt][nt], af[mt], bf[nt][0], bf[nt][1]);
    }

    // Epilogue
#pragma unroll
    for (int nt = 0; nt < 4; nt++) {
        int c = colBase + wn + nt * 8 + 2 * lc;
        float2 bv = *(const float2*)&bias[c];
#pragma unroll
        for (int mt = 0; mt < 4; mt++) {
            int r0 = rowBase + wm + mt * 16 + lr;
            int r1 = r0 + 8;
            float v00 = acc[mt][nt][0] + bv.x, v01 = acc[mt][nt][1] + bv.y;
            float v10 = acc[mt][nt][2] + bv.x, v11 = acc[mt][nt][3] + bv.y;
            if (MODE == 0) {
                int which = c >> 10;
                int c2    = c & 1023;
                int head  = c2 >> 6;
                int d     = c2 & 63;
                if (which == 0) {
                    __half* dq = g_q + ((size_t)head * SEQ) * HD + pidx(d);
                    *(__half2*)&dq[(size_t)r0 * HD] = __floats2half2_rn(v00 * 0.125f, v01 * 0.125f);
                    *(__half2*)&dq[(size_t)r1 * HD] = __floats2half2_rn(v10 * 0.125f, v11 * 0.125f);
                } else if (which == 1) {
                    __half* dk = g_k + ((size_t)head * SEQ) * HD + pidx(d);
                    *(__half2*)&dk[(size_t)r0 * HD] = __floats2half2_rn(v00, v01);
                    *(__half2*)&dk[(size_t)r1 * HD] = __floats2half2_rn(v10, v11);
                } else {
                    __half* dv = g_v + (size_t)head * HD * SEQ;
                    int p0 = pidx(r0 & 4095), p1 = pidx(r1 & 4095);
                    dv[(size_t)(d)     * SEQ + p0] = __float2half_rn(v00);
                    dv[(size_t)(d + 1) * SEQ + p0] = __float2half_rn(v01);
                    dv[(size_t)(d)     * SEQ + p1] = __float2half_rn(v10);
                    dv[(size_t)(d + 1) * SEQ + p1] = __float2half_rn(v11);
                }
            } else {
                *(float2*)&C[(size_t)r0 * N_ + c] = make_float2(v00, v01);
                *(float2*)&C[(size_t)r1 * N_ + c] = make_float2(v10, v11);
            }
        }
    }
}

// ---------------------------------------------------------------------------
// fp16 warp-MMA flash attention (round-12 body). Epilogue writes fp16
// pidx-permuted g_att (the proj GEMM's A operand).
// ---------------------------------------------------------------------------
#define HSTR 72
#define STAGE_H (2 * 64 * HSTR)        // 9216 halves per stage (K+V)
#define STAGE_B (STAGE_H * 2)          // 18432 bytes
#define ATTN_SM_B (3 * STAGE_B)        // 55296 bytes

__global__ __launch_bounds__(128) void attn_mma() {
    extern __shared__ __half smh[];
    const uint32_t sb = smem_u32(smh);

    const int t    = threadIdx.x;
    const int lane = t & 31;
    const int lr   = lane >> 2;
    const int lc   = lane & 3;
    const int w16  = (t >> 5) * 16;
    const int h  = blockIdx.y;
    const int qt = blockIdx.x;

    const __half* Kh = g_k + (size_t)h * SEQ * HD;   // [key][d-permuted]
    const __half* Vh = g_v + (size_t)h * HD * SEQ;   // [d][key-permuted]

    auto load_stage = [&](int kt2, int s) {
#pragma unroll
        for (int i = 0; i < 8; i++) {
            int id   = t + i * 128;            // 0..1023 (16B units)
            int tile = id >> 9;                // 0=K 1=V
            int r    = (id >> 3) & 63;
            int c4   = id & 7;
            uint32_t dst = sb + (uint32_t)s * STAGE_B
                              + (uint32_t)tile * (64 * HSTR * 2)
                              + (uint32_t)r * (HSTR * 2) + (uint32_t)c4 * 16;
            const __half* src = tile
                ? Vh + (size_t)r * SEQ + (size_t)kt2 * 64 + c4 * 8
                : Kh + ((size_t)kt2 * 64 + r) * HD + c4 * 8;
            cp16(dst, src);
        }
        CP_COMMIT();
    };

    load_stage(0, 0);
    load_stage(1, 1);

    // Stage 64 Q rows through the (not yet filled) stage-2 buffer
    __half* Qs = smh + 2 * STAGE_H;
    {
        const __half* Qg = g_q + ((size_t)h * SEQ + (size_t)qt * 64) * HD;
#pragma unroll
        for (int i = 0; i < 4; i++) {
            int id = t + i * 128;
            int r  = id >> 3;
            int c4 = id & 7;
            *(float4*)&Qs[r * HSTR + c4 * 8] = *(const float4*)&Qg[(size_t)r * HD + c4 * 8];
        }
    }
    __syncthreads();
    uint32_t qf[4][4];
#pragma unroll
    for (int G = 0; G < 4; G++) {
        uint2 a02 = *(const uint2*)&Qs[(w16 + lr) * HSTR + G * 16 + lc * 4];
        uint2 a13 = *(const uint2*)&Qs[(w16 + lr + 8) * HSTR + G * 16 + lc * 4];
        qf[G][0] = a02.x; qf[G][2] = a02.y;
        qf[G][1] = a13.x; qf[G][3] = a13.y;
    }
    // iter-0's loop-top barrier orders these reads before stage-2's first fill

    float ob[8][4];
#pragma unroll
    for (int j = 0; j < 8; j++)
#pragma unroll
        for (int i = 0; i < 4; i++) ob[j][i] = 0.f;
    float accl[4] = {0.f, 0.f, 0.f, 0.f};
    const uint32_t bl2 = (lr == 0) ? 0x3C003C00u : 0u;
    float m0 = -1e30f, m1 = -1e30f;

    for (int kt = 0; kt < SEQ / 64; kt++) {
        const int s = kt % 3;
        const __half* Ks = smh + s * STAGE_H;
        const __half* Vs = Ks + 64 * HSTR;

        CP_WAITG1();
        __syncthreads();

        if (kt + 2 < SEQ / 64) load_stage(kt + 2, (kt + 2) % 3);
        else CP_COMMIT();

        // ---- S = Q * K^T ----
        float sc[8][4];
#pragma unroll
        for (int j = 0; j < 8; j++)
#pragma unroll
            for (int i = 0; i < 4; i++) sc[j][i] = 0.f;
#pragma unroll
        for (int G = 0; G < 4; G++) {
#pragma unroll
            for (int j = 0; j < 8; j++) {
                uint2 b = *(const uint2*)&Ks[(j * 8 + lr) * HSTR + G * 16 + lc * 4];
                mma_f16(sc[j], qf[G], b.x, b.y);
            }
        }

        // ---- online softmax, P stays in registers ----
        float mx0 = sc[0][0], mx1 = sc[0][2];
#pragma unroll
        for (int j = 0; j < 8; j++) {
            mx0 = fmaxf(mx0, fmaxf(sc[j][0], sc[j][1]));
            mx1 = fmaxf(mx1, fmaxf(sc[j][2], sc[j][3]));
        }
        mx0 = fmaxf(mx0, __shfl_xor_sync(0xffffffffu, mx0, 1));
        mx0 = fmaxf(mx0, __shfl_xor_sync(0xffffffffu, mx0, 2));
        mx1 = fmaxf(mx1, __shfl_xor_sync(0xffffffffu, mx1, 1));
        mx1 = fmaxf(mx1, __shfl_xor_sync(0xffffffffu, mx1, 2));
        float nm0 = fmaxf(m0, mx0), nm1 = fmaxf(m1, mx1);
        float corr0 = ex2f((m0 - nm0) * LOG2E);
        float corr1 = ex2f((m1 - nm1) * LOG2E);
#pragma unroll
        for (int j = 0; j < 8; j++) {
            sc[j][0] = ex2f((sc[j][0] - nm0) * LOG2E);
            sc[j][1] = ex2f((sc[j][1] - nm0) * LOG2E);
            sc[j][2] = ex2f((sc[j][2] - nm1) * LOG2E);
            sc[j][3] = ex2f((sc[j][3] - nm1) * LOG2E);
        }
        m0 = nm0; m1 = nm1;
#pragma unroll
        for (int j = 0; j < 8; j++) {
            ob[j][0] *= corr0; ob[j][1] *= corr0;
            ob[j][2] *= corr1; ob[j][3] *= corr1;
        }
        accl[0] *= corr0; accl[2] *= corr1;

        // ---- O += P*V ; l += P*1 ----
#pragma unroll
        for (int J = 0; J < 4; J++) {
            uint32_t pf[4];
            pf[0] = pack2(sc[2 * J][0],     sc[2 * J][1]);
            pf[1] = pack2(sc[2 * J][2],     sc[2 * J][3]);
            pf[2] = pack2(sc[2 * J + 1][0], sc[2 * J + 1][1]);
            pf[3] = pack2(sc[2 * J + 1][2], sc[2 * J + 1][3]);
#pragma unroll
            for (int j = 0; j < 8; j++) {
                uint2 b = *(const uint2*)&Vs[(j * 8 + lr) * HSTR + J * 16 + lc * 4];
                mma_f16(ob[j], pf, b.x, b.y);
            }
            mma_f16(accl, pf, bl2, bl2);
        }
    }

    float l0 = __shfl_sync(0xffffffffu, accl[0], lane & 28);
    float l1 = __shfl_sync(0xffffffffu, accl[2], lane & 28);
    float inv0 = 1.f / l0, inv1 = 1.f / l1;
    const int row0 = qt * 64 + w16 + lr;
#pragma unroll
    for (int j = 0; j < 8; j++) {
        // natural col c = h*64 + j*8 + 2lc -> fp16, pidx-permuted (proj A format)
        int pl  = 4 * (j & 1) + lc;
        int col = h * 64 + (j >> 1) * 16 + ppair(pl) * 2;
        *(__half2*)&g_att[(size_t)row0 * DIM + col] =
            __floats2half2_rn(ob[j][0] * inv0, ob[j][1] * inv0);
        *(__half2*)&g_att[(size_t)(row0 + 8) * DIM + col] =
            __floats2half2_rn(ob[j][2] * inv1, ob[j][3] * inv1);
    }
}

// ---------------------------------------------------------------------------
extern "C" void kernel_launch(void* const* d_in, const int* in_sizes, int n_in,
                              void* d_out, int out_size) {
    const float* x     = (const float*)d_in[0];
    const float* Wqkv  = (const float*)d_in[1];
    const float* bqkv  = (const float*)d_in[2];
    const float* Wproj = (const float*)d_in[3];
    const float* bproj = (const float*)d_in[4];
    float* out = (float*)d_out;

    const int gemm_shm = 3 * GSTG_B;       // 31488 B
    const int attn_shm = ATTN_SM_B;        // 55296 B

    // 0) pack x / W_qkv / W_proj to fp16 MMA layouts
    pack_inputs<<<(int)((PACK_T + 255) / 256), 256>>>(x, Wqkv, Wproj);

    // 1) QKV projection (fp16 MMA) -> fp16 q (scaled), k, v (permuted layouts)
    cudaFuncSetAttribute(gemm_tc<3 * DIM, 0>, cudaFuncAttributeMaxDynamicSharedMemorySize, gemm_shm);
    gemm_tc<3 * DIM, 0><<<dim3(24, 32), 256, gemm_shm>>>(bqkv, nullptr);

    // 2) fp16 warp-MMA flash attention
    cudaFuncSetAttribute(attn_mma, cudaFuncAttributeMaxDynamicSharedMemorySize, attn_shm);
    attn_mma<<<dim3(SEQ / 64, NH), 128, attn_shm>>>();

    // 3) Output projection (fp16 MMA)
    cudaFuncSetAttribute(gemm_tc<DIM, 1>, cudaFuncAttributeMaxDynamicSharedMemorySize, gemm_shm);
    gemm_tc<DIM, 1><<<dim3(8, 32), 256, gemm_shm>>>(bproj, out);
}

// round 15
// speedup vs baseline: 1.6477x; 1.0825x over previous
#include <cuda_runtime.h>
#include <cuda_fp16.h>
#include <cstdint>

#define SEQ  4096
#define DIM  1024
#define NH   16
#define HD   64

// Scratch (allocation-free rule: __device__ globals)
__device__ __half  g_q[(size_t)NH * SEQ * HD];   // [H][SEQ][HD] fp16, x0.125, d pair-permuted
__device__ __half  g_k[(size_t)NH * SEQ * HD];   // [H][SEQ][HD] fp16, d pair-permuted
__device__ __half  g_v[(size_t)NH * HD * SEQ];   // [H][HD][SEQ] fp16 (d-major), seq pair-permuted
__device__ __half  g_att[(size_t)SEQ * DIM];     // fp16, k pair-permuted (proj A operand)
__device__ __half  g_xh[(size_t)SEQ * DIM];      // fp16 x, k pair-permuted
__device__ __half2 g_wqp[(size_t)(DIM / 2) * 3 * DIM]; // W_qkv k-pair-packed [K/2][3N]
__device__ __half2 g_wpp[(size_t)(DIM / 2) * DIM];     // W_proj k-pair-packed

// ---------------------------------------------------------------------------
__device__ __forceinline__ uint32_t smem_u32(const void* p) {
    uint32_t a;
    asm("{ .reg .u64 t; cvta.to.shared.u64 t, %1; cvt.u32.u64 %0, t; }" : "=r"(a) : "l"(p));
    return a;
}
__device__ __forceinline__ float ex2f(float x) {
    float r; asm("ex2.approx.ftz.f32 %0, %1;" : "=f"(r) : "f"(x)); return r;
}
__device__ __forceinline__ void cp16(uint32_t dst, const void* src) {
    asm volatile("cp.async.cg.shared.global [%0], [%1], 16;" :: "r"(dst), "l"(src));
}
#define CP_COMMIT() asm volatile("cp.async.commit_group;" ::: "memory")
#define CP_WAITG1() asm volatile("cp.async.wait_group 1;" ::: "memory")

__device__ __forceinline__ void mma_f16(float* d, const uint32_t* a, uint32_t b0, uint32_t b1) {
    asm volatile(
        "mma.sync.aligned.m16n8k16.row.col.f32.f16.f16.f32 "
        "{%0,%1,%2,%3}, {%4,%5,%6,%7}, {%8,%9}, {%0,%1,%2,%3};"
        : "+f"(d[0]), "+f"(d[1]), "+f"(d[2]), "+f"(d[3])
        : "r"(a[0]), "r"(a[1]), "r"(a[2]), "r"(a[3]), "r"(b0), "r"(b1));
}

__device__ __forceinline__ uint32_t pack2(float x, float y) {
    __half2 h = __floats2half2_rn(x, y);
    return *(uint32_t*)&h;
}

// Pair permutation within 16-groups: natural pair p (0..7) -> phys pair.
__device__ __forceinline__ int ppair(int p) { return (p < 4) ? 2 * p : 2 * p - 7; }
__device__ __forceinline__ int pidx(int i) {
    int p = (i & 15) >> 1;
    return (i & ~15) | (ppair(p) * 2 + (i & 1));
}

#define LOG2E 1.44269504f

// ---------------------------------------------------------------------------
// Pack inputs to fp16 attention/GEMM layouts (round-14, unchanged).
// ---------------------------------------------------------------------------
#define XT  ((size_t)SEQ * DIM / 4)
#define WQT ((size_t)(DIM / 2) * 3 * DIM / 4)
#define WPT ((size_t)(DIM / 2) * DIM / 4)
#define PACK_T (XT + WQT + WPT)

__global__ __launch_bounds__(256) void pack_inputs(const float* __restrict__ x,
                                                   const float* __restrict__ wq,
                                                   const float* __restrict__ wp) {
    size_t i = (size_t)blockIdx.x * blockDim.x + threadIdx.x;
    if (i >= PACK_T) return;
    if (i < XT) {
        int row = (int)(i >> 8);
        int c   = ((int)i & 255) << 2;
        float4 v = *(const float4*)&x[(size_t)row * DIM + c];
        int pl = (c & 15) >> 1;
        __half2* dst = (__half2*)g_xh + ((size_t)row * DIM + (c & ~15)) / 2;
        dst[ppair(pl)]     = __floats2half2_rn(v.x, v.y);
        dst[ppair(pl + 1)] = __floats2half2_rn(v.z, v.w);
    } else if (i < XT + WQT) {
        size_t j = i - XT;
        int p = (int)(j / 768);
        int c = ((int)(j % 768)) * 4;
        float4 a = *(const float4*)&wq[(size_t)(2 * p) * (3 * DIM) + c];
        float4 b = *(const float4*)&wq[(size_t)(2 * p + 1) * (3 * DIM) + c];
        __half2* dst = g_wqp + (size_t)p * (3 * DIM) + c;
        dst[0] = __floats2half2_rn(a.x, b.x);
        dst[1] = __floats2half2_rn(a.y, b.y);
        dst[2] = __floats2half2_rn(a.z, b.z);
        dst[3] = __floats2half2_rn(a.w, b.w);
    } else {
        size_t j = i - XT - WQT;
        int p = (int)(j >> 8);
        int c = ((int)j & 255) * 4;
        float4 a = *(const float4*)&wp[(size_t)(2 * p) * DIM + c];
        float4 b = *(const float4*)&wp[(size_t)(2 * p + 1) * DIM + c];
        __half2* dst = g_wpp + (size_t)p * DIM + c;
        dst[0] = __floats2half2_rn(a.x, b.x);
        dst[1] = __floats2half2_rn(a.y, b.y);
        dst[2] = __floats2half2_rn(a.z, b.z);
        dst[3] = __floats2half2_rn(a.w, b.w);
    }
}

// ---------------------------------------------------------------------------
// fp16 warp-MMA GEMM (round-14, unchanged).
// ---------------------------------------------------------------------------
#define ASTRH 24
#define BSTRH 136
#define A_ST_B (128 * ASTRH * 2)
#define B_ST_B (8 * BSTRH * 4)
#define GSTG_B (A_ST_B + B_ST_B)
#define NCHUNK (DIM / 16)

template <int N_, int MODE>
__global__ __launch_bounds__(256) void gemm_tc(const float* __restrict__ bias,
                                               float* __restrict__ C) {
    extern __shared__ char smc[];
    const uint32_t sb = smem_u32(smc);
    const __half*  A  = (MODE == 1) ? g_att : g_xh;
    const __half2* Bp = (MODE == 1) ? g_wpp : g_wqp;

    const int t    = threadIdx.x;
    const int w    = t >> 5;
    const int lane = t & 31;
    const int lr   = lane >> 2;
    const int lc   = lane & 3;
    const int wm   = (w >> 2) * 64;
    const int wn   = (w & 3) * 32;
    const int rowBase = blockIdx.y * 128;
    const int colBase = blockIdx.x * 128;

    auto load_chunk = [&](int k0, int s) {
        uint32_t base = sb + (uint32_t)s * GSTG_B;
        {
            int r = t >> 1, u = t & 1;
            cp16(base + (uint32_t)r * (ASTRH * 2) + (uint32_t)u * 16,
                 A + (size_t)(rowBase + r) * DIM + k0 + u * 8);
        }
        {
            int pr = t >> 5, c4 = t & 31;
            cp16(base + A_ST_B + (uint32_t)pr * (BSTRH * 4) + (uint32_t)c4 * 16,
                 Bp + (size_t)(k0 / 2 + pr) * N_ + colBase + c4 * 4);
        }
        CP_COMMIT();
    };

    load_chunk(0, 0);
    load_chunk(16, 1);

    float acc[4][4][4];
#pragma unroll
    for (int mt = 0; mt < 4; mt++)
#pragma unroll
        for (int nt = 0; nt < 4; nt++)
#pragma unroll
            for (int i = 0; i < 4; i++) acc[mt][nt][i] = 0.f;

    for (int kc = 0; kc < NCHUNK; kc++) {
        const int s = kc % 3;
        const __half*  As = (const __half*)(smc + (size_t)s * GSTG_B);
        const __half2* Bs = (const __half2*)(smc + (size_t)s * GSTG_B + A_ST_B);

        CP_WAITG1();
        __syncthreads();

        if (kc + 2 < NCHUNK) load_chunk((kc + 2) * 16, (kc + 2) % 3);
        else CP_COMMIT();

        uint32_t af[4][4];
#pragma unroll
        for (int mt = 0; mt < 4; mt++) {
            int mb = wm + mt * 16;
            uint2 a0 = *(const uint2*)&As[(mb + lr) * ASTRH + lc * 4];
            uint2 a1 = *(const uint2*)&As[(mb + lr + 8) * ASTRH + lc * 4];
            af[mt][0] = a0.x; af[mt][1] = a1.x;
            af[mt][2] = a0.y; af[mt][3] = a1.y;
        }
        uint32_t bf[4][2];
#pragma unroll
        for (int nt = 0; nt < 4; nt++) {
            int n = wn + nt * 8 + lr;
            bf[nt][0] = *(const uint32_t*)&Bs[lc * BSTRH + n];
            bf[nt][1] = *(const uint32_t*)&Bs[(lc + 4) * BSTRH + n];
        }
#pragma unroll
        for (int mt = 0; mt < 4; mt++)
#pragma unroll
            for (int nt = 0; nt < 4; nt++)
                mma_f16(acc[mt][nt], af[mt], bf[nt][0], bf[nt][1]);
    }

    // Epilogue
#pragma unroll
    for (int nt = 0; nt < 4; nt++) {
        int c = colBase + wn + nt * 8 + 2 * lc;
        float2 bv = *(const float2*)&bias[c];
#pragma unroll
        for (int mt = 0; mt < 4; mt++) {
            int r0 = rowBase + wm + mt * 16 + lr;
            int r1 = r0 + 8;
            float v00 = acc[mt][nt][0] + bv.x, v01 = acc[mt][nt][1] + bv.y;
            float v10 = acc[mt][nt][2] + bv.x, v11 = acc[mt][nt][3] + bv.y;
            if (MODE == 0) {
                int which = c >> 10;
                int c2    = c & 1023;
                int head  = c2 >> 6;
                int d     = c2 & 63;
                if (which == 0) {
                    __half* dq = g_q + ((size_t)head * SEQ) * HD + pidx(d);
                    *(__half2*)&dq[(size_t)r0 * HD] = __floats2half2_rn(v00 * 0.125f, v01 * 0.125f);
                    *(__half2*)&dq[(size_t)r1 * HD] = __floats2half2_rn(v10 * 0.125f, v11 * 0.125f);
                } else if (which == 1) {
                    __half* dk = g_k + ((size_t)head * SEQ) * HD + pidx(d);
                    *(__half2*)&dk[(size_t)r0 * HD] = __floats2half2_rn(v00, v01);
                    *(__half2*)&dk[(size_t)r1 * HD] = __floats2half2_rn(v10, v11);
                } else {
                    __half* dv = g_v + (size_t)head * HD * SEQ;
                    int p0 = pidx(r0 & 4095), p1 = pidx(r1 & 4095);
                    dv[(size_t)(d)     * SEQ + p0] = __float2half_rn(v00);
                    dv[(size_t)(d + 1) * SEQ + p0] = __float2half_rn(v01);
                    dv[(size_t)(d)     * SEQ + p1] = __float2half_rn(v10);
                    dv[(size_t)(d + 1) * SEQ + p1] = __float2half_rn(v11);
                }
            } else {
                *(float2*)&C[(size_t)r0 * N_ + c] = make_float2(v00, v01);
                *(float2*)&C[(size_t)r1 * N_ + c] = make_float2(v10, v11);
            }
        }
    }
}

// ---------------------------------------------------------------------------
// fp16 warp-MMA flash attention, 32 q-rows/warp (2 m-tiles): every K/V
// B-fragment LDS.64 feeds TWO MMAs. Register-resident P, 3-stage pipeline,
// 1 barrier/iter. Block = 128 q-rows x head, 128 threads (4 warps).
// ---------------------------------------------------------------------------
#define HSTR 72
#define STAGE_H (2 * 64 * HSTR)        // 9216 halves per stage (K+V)
#define STAGE_B (STAGE_H * 2)          // 18432 bytes
#define ATTN_SM_B (3 * STAGE_B)        // 55296 bytes

__global__ __launch_bounds__(128, 2) void attn_mma() {
    extern __shared__ __half smh[];
    const uint32_t sb = smem_u32(smh);

    const int t    = threadIdx.x;
    const int lane = t & 31;
    const int lr   = lane >> 2;
    const int lc   = lane & 3;
    const int rb   = (t >> 5) * 32;    // warp's 32-row base
    const int h  = blockIdx.y;
    const int qt = blockIdx.x;

    const __half* Kh = g_k + (size_t)h * SEQ * HD;   // [key][d-permuted]
    const __half* Vh = g_v + (size_t)h * HD * SEQ;   // [d][key-permuted]

    auto load_stage = [&](int kt2, int s) {
#pragma unroll
        for (int i = 0; i < 8; i++) {
            int id   = t + i * 128;            // 0..1023 (16B units)
            int tile = id >> 9;                // 0=K 1=V
            int r    = (id >> 3) & 63;
            int c4   = id & 7;
            uint32_t dst = sb + (uint32_t)s * STAGE_B
                              + (uint32_t)tile * (64 * HSTR * 2)
                              + (uint32_t)r * (HSTR * 2) + (uint32_t)c4 * 16;
            const __half* src = tile
                ? Vh + (size_t)r * SEQ + (size_t)kt2 * 64 + c4 * 8
                : Kh + ((size_t)kt2 * 64 + r) * HD + c4 * 8;
            cp16(dst, src);
        }
        CP_COMMIT();
    };

    load_stage(0, 0);
    load_stage(1, 1);

    // Stage 128 Q rows through the (not yet filled) stage-2 buffer (fits exactly)
    __half* Qs = smh + 2 * STAGE_H;
    {
        const __half* Qg = g_q + ((size_t)h * SEQ + (size_t)qt * 128) * HD;
#pragma unroll
        for (int i = 0; i < 8; i++) {
            int id = t + i * 128;              // 16B units, 0..1023
            int r  = id >> 3;                  // 0..127
            int c4 = id & 7;
            *(float4*)&Qs[r * HSTR + c4 * 8] = *(const float4*)&Qg[(size_t)r * HD + c4 * 8];
        }
    }
    __syncthreads();
    uint32_t qf[2][4][4];
#pragma unroll
    for (int mt = 0; mt < 2; mt++)
#pragma unroll
        for (int G = 0; G < 4; G++) {
            uint2 a02 = *(const uint2*)&Qs[(rb + mt * 16 + lr) * HSTR + G * 16 + lc * 4];
            uint2 a13 = *(const uint2*)&Qs[(rb + mt * 16 + lr + 8) * HSTR + G * 16 + lc * 4];
            qf[mt][G][0] = a02.x; qf[mt][G][2] = a02.y;
            qf[mt][G][1] = a13.x; qf[mt][G][3] = a13.y;
        }
    // iter-0's loop-top barrier orders these reads before stage-2's first fill

    float ob[2][8][4];
#pragma unroll
    for (int mt = 0; mt < 2; mt++)
#pragma unroll
        for (int j = 0; j < 8; j++)
#pragma unroll
            for (int i = 0; i < 4; i++) ob[mt][j][i] = 0.f;
    float accl[2][4] = {{0.f, 0.f, 0.f, 0.f}, {0.f, 0.f, 0.f, 0.f}};
    const uint32_t bl2 = (lr == 0) ? 0x3C003C00u : 0u;
    float m0[2] = {-1e30f, -1e30f}, m1[2] = {-1e30f, -1e30f};

    for (int kt = 0; kt < SEQ / 64; kt++) {
        const int s = kt % 3;
        const __half* Ks = smh + s * STAGE_H;
        const __half* Vs = Ks + 64 * HSTR;

        CP_WAITG1();          // tile kt resident
        __syncthreads();      // all warps past iter kt-1

        if (kt + 2 < SEQ / 64) load_stage(kt + 2, (kt + 2) % 3);
        else CP_COMMIT();

        // ---- S = Q * K^T : each K fragment feeds both m-tiles ----
        float sc[2][8][4];
#pragma unroll
        for (int mt = 0; mt < 2; mt++)
#pragma unroll
            for (int j = 0; j < 8; j++)
#pragma unroll
                for (int i = 0; i < 4; i++) sc[mt][j][i] = 0.f;
#pragma unroll
        for (int G = 0; G < 4; G++) {
#pragma unroll
            for (int j = 0; j < 8; j++) {
                uint2 b = *(const uint2*)&Ks[(j * 8 + lr) * HSTR + G * 16 + lc * 4];
                mma_f16(sc[0][j], qf[0][G], b.x, b.y);
                mma_f16(sc[1][j], qf[1][G], b.x, b.y);
            }
        }

        // ---- online softmax per m-tile (P stays in sc registers) ----
#pragma unroll
        for (int mt = 0; mt < 2; mt++) {
            float mx0 = sc[mt][0][0], mx1 = sc[mt][0][2];
#pragma unroll
            for (int j = 0; j < 8; j++) {
                mx0 = fmaxf(mx0, fmaxf(sc[mt][j][0], sc[mt][j][1]));
                mx1 = fmaxf(mx1, fmaxf(sc[mt][j][2], sc[mt][j][3]));
            }
            mx0 = fmaxf(mx0, __shfl_xor_sync(0xffffffffu, mx0, 1));
            mx0 = fmaxf(mx0, __shfl_xor_sync(0xffffffffu, mx0, 2));
            mx1 = fmaxf(mx1, __shfl_xor_sync(0xffffffffu, mx1, 1));
            mx1 = fmaxf(mx1, __shfl_xor_sync(0xffffffffu, mx1, 2));
            float nm0 = fmaxf(m0[mt], mx0), nm1 = fmaxf(m1[mt], mx1);
            float corr0 = ex2f((m0[mt] - nm0) * LOG2E);
            float corr1 = ex2f((m1[mt] - nm1) * LOG2E);
#pragma unroll
            for (int j = 0; j < 8; j++) {
                sc[mt][j][0] = ex2f((sc[mt][j][0] - nm0) * LOG2E);
                sc[mt][j][1] = ex2f((sc[mt][j][1] - nm0) * LOG2E);
                sc[mt][j][2] = ex2f((sc[mt][j][2] - nm1) * LOG2E);
                sc[mt][j][3] = ex2f((sc[mt][j][3] - nm1) * LOG2E);
            }
            m0[mt] = nm0; m1[mt] = nm1;
#pragma unroll
            for (int j = 0; j < 8; j++) {
                ob[mt][j][0] *= corr0; ob[mt][j][1] *= corr0;
                ob[mt][j][2] *= corr1; ob[mt][j][3] *= corr1;
            }
            accl[mt][0] *= corr0; accl[mt][2] *= corr1;
        }

        // ---- O += P*V ; l += P*1 : each V fragment feeds both m-tiles ----
#pragma unroll
        for (int J = 0; J < 4; J++) {
            uint32_t pf0[4], pf1[4];
            pf0[0] = pack2(sc[0][2 * J][0],     sc[0][2 * J][1]);
            pf0[1] = pack2(sc[0][2 * J][2],     sc[0][2 * J][3]);
            pf0[2] = pack2(sc[0][2 * J + 1][0], sc[0][2 * J + 1][1]);
            pf0[3] = pack2(sc[0][2 * J + 1][2], sc[0][2 * J + 1][3]);
            pf1[0] = pack2(sc[1][2 * J][0],     sc[1][2 * J][1]);
            pf1[1] = pack2(sc[1][2 * J][2],     sc[1][2 * J][3]);
            pf1[2] = pack2(sc[1][2 * J + 1][0], sc[1][2 * J + 1][1]);
            pf1[3] = pack2(sc[1][2 * J + 1][2], sc[1][2 * J + 1][3]);
#pragma unroll
            for (int j = 0; j < 8; j++) {
                uint2 b = *(const uint2*)&Vs[(j * 8 + lr) * HSTR + J * 16 + lc * 4];
                mma_f16(ob[0][j], pf0, b.x, b.y);
                mma_f16(ob[1][j], pf1, b.x, b.y);
            }
            mma_f16(accl[0], pf0, bl2, bl2);
            mma_f16(accl[1], pf1, bl2, bl2);
        }
    }

#pragma unroll
    for (int mt = 0; mt < 2; mt++) {
        float l0 = __shfl_sync(0xffffffffu, accl[mt][0], lane & 28);
        float l1 = __shfl_sync(0xffffffffu, accl[mt][2], lane & 28);
        float inv0 = 1.f / l0, inv1 = 1.f / l1;
        const int row0 = qt * 128 + rb + mt * 16 + lr;
#pragma unroll
        for (int j = 0; j < 8; j++) {
            int pl  = 4 * (j & 1) + lc;
            int col = h * 64 + (j >> 1) * 16 + ppair(pl) * 2;
            *(__half2*)&g_att[(size_t)row0 * DIM + col] =
                __floats2half2_rn(ob[mt][j][0] * inv0, ob[mt][j][1] * inv0);
            *(__half2*)&g_att[(size_t)(row0 + 8) * DIM + col] =
                __floats2half2_rn(ob[mt][j][2] * inv1, ob[mt][j][3] * inv1);
        }
    }
}

// ---------------------------------------------------------------------------
extern "C" void kernel_launch(void* const* d_in, const int* in_sizes, int n_in,
                              void* d_out, int out_size) {
    const float* x     = (const float*)d_in[0];
    const float* Wqkv  = (const float*)d_in[1];
    const float* bqkv  = (const float*)d_in[2];
    const float* Wproj = (const float*)d_in[3];
    const float* bproj = (const float*)d_in[4];
    float* out = (float*)d_out;

    const int gemm_shm = 3 * GSTG_B;       // 31488 B
    const int attn_shm = ATTN_SM_B;        // 55296 B

    // 0) pack x / W_qkv / W_proj to fp16 MMA layouts
    pack_inputs<<<(int)((PACK_T + 255) / 256), 256>>>(x, Wqkv, Wproj);

    // 1) QKV projection (fp16 MMA)
    cudaFuncSetAttribute(gemm_tc<3 * DIM, 0>, cudaFuncAttributeMaxDynamicSharedMemorySize, gemm_shm);
    gemm_tc<3 * DIM, 0><<<dim3(24, 32), 256, gemm_shm>>>(bqkv, nullptr);

    // 2) fp16 warp-MMA flash attention (32 q-rows/warp)
    cudaFuncSetAttribute(attn_mma, cudaFuncAttributeMaxDynamicSharedMemorySize, attn_shm);
    attn_mma<<<dim3(SEQ / 128, NH), 128, attn_shm>>>();

    // 3) Output projection (fp16 MMA)
    cudaFuncSetAttribute(gemm_tc<DIM, 1>, cudaFuncAttributeMaxDynamicSharedMemorySize, gemm_shm);
    gemm_tc<DIM, 1><<<dim3(8, 32), 256, gemm_shm>>>(bproj, out);
}